// round 15
// baseline (speedup 1.0000x reference)
#include <cuda_runtime.h>
#include <cstdint>
#include <cstddef>

#define NB   32
#define NS   512
#define ND   512
#define NH2  256
#define NG3  768
#define NDK  64

// ------------------------- scratch (device globals) -------------------------
__device__ float g_xg[(size_t)2 * NB * NS * NG3];   // gate preactivations, per dir
__device__ float g_gru[(size_t)NB * NS * ND];       // concat GRU outputs
__device__ float g_ln1[(size_t)NB * NS * ND];       // ln1("outputs")
__device__ float g_q [(size_t)NB * 8 * NS * NDK];   // (b,h,s,d)
__device__ float g_k [(size_t)NB * 8 * NS * NDK];   // (b,h,s,d)
__device__ float g_vt[(size_t)NB * 8 * NDK * NS];   // (b,h,d,s)
__device__ float g_cc[(size_t)NB * NS * ND];        // attn concat
__device__ float g_o [(size_t)NB * NS * ND];        // out projection
__device__ float g_hx[16 * 2048];                   // h exchange (16 groups x 2 bufs x 1024)
__device__ unsigned g_flag[16 * 8 * 32];            // per (group,rank) step flag, 1 per 128B line

// ------------------------- helpers -------------------------
__device__ __forceinline__ unsigned long long fma2(unsigned long long a,
                                                   unsigned long long b,
                                                   unsigned long long c) {
    unsigned long long d;
    asm("fma.rn.f32x2 %0, %1, %2, %3;" : "=l"(d) : "l"(a), "l"(b), "l"(c));
    return d;
}
__device__ __forceinline__ unsigned long long pack2(float x, float y) {
    unsigned long long d;
    asm("mov.b64 %0, {%1, %2};" : "=l"(d) : "f"(x), "f"(y));
    return d;
}
__device__ __forceinline__ void unpack2(unsigned long long v, float& x, float& y) {
    asm("mov.b64 {%0, %1}, %2;" : "=f"(x), "=f"(y) : "l"(v));
}
__device__ __forceinline__ float tf32r(float f) {
    unsigned u;
    asm("cvt.rna.tf32.f32 %0, %1;" : "=r"(u) : "f"(f));
    return __uint_as_float(u);
}
__device__ __forceinline__ void mma_tf32(float* acc, const unsigned* a, const unsigned* b) {
    asm volatile(
        "mma.sync.aligned.m16n8k8.row.col.f32.tf32.tf32.f32 "
        "{%0,%1,%2,%3}, {%4,%5,%6,%7}, {%8,%9}, {%0,%1,%2,%3};"
        : "+f"(acc[0]), "+f"(acc[1]), "+f"(acc[2]), "+f"(acc[3])
        : "r"(a[0]), "r"(a[1]), "r"(a[2]), "r"(a[3]),
          "r"(b[0]), "r"(b[1]));
}

// ------------------------- epilogue store -------------------------
// 0: +bias   1: +bias, scatter (b,h,s,d)   2: +bias, scatter (b,h,d,s)
// 5: +bias, *rowmask(masks)
__device__ __forceinline__ void store_elem(float* C, const float* bias,
                                           const int* masks, int mode,
                                           int N, int mrow, int nc, float v) {
    if (mode == 0) {
        C[(size_t)mrow * N + nc] = v + bias[nc];
    } else if (mode == 1) {
        int b = mrow >> 9, s = mrow & 511, h = nc >> 6, d = nc & 63;
        C[(((size_t)(b * 8 + h) * NS + s)) * NDK + d] = v + bias[nc];
    } else if (mode == 2) {
        int b = mrow >> 9, s = mrow & 511, h = nc >> 6, d = nc & 63;
        C[((size_t)(b * 8 + h) * NDK + d) * NS + s] = v + bias[nc];
    } else {
        C[(size_t)mrow * N + nc] = masks[mrow] ? (v + bias[nc]) : 0.f;
    }
}

// ------------------------- tf32 TN GEMM, double-buffered, up to 3 ops/z -----
// C = epi(A[M,K] @ W[N,K]^T). Requires M%128==0, N%128==0, K%32==0.
// 128x128x32 tile, 2-stage smem pipeline, 1 syncthreads per K-chunk.
#define G3_SMEM (2 * 2 * 128 * 36 * 4)
__global__ void __launch_bounds__(256) gemm3(
    const float* __restrict__ A,
    const float* __restrict__ W0, const float* __restrict__ W1, const float* __restrict__ W2,
    const float* __restrict__ b0, const float* __restrict__ b1, const float* __restrict__ b2,
    float* __restrict__ C0, float* __restrict__ C1, float* __restrict__ C2,
    int mode0, int mode1, int mode2,
    int M, int N, int K, const int* __restrict__ masks)
{
    extern __shared__ float smg[];
    float* Asm = smg;                 // [2][128][36]
    float* Wsm = smg + 2 * 128 * 36;  // [2][128][36]

    const int z = blockIdx.z;
    const float* W    = (z == 0) ? W0 : (z == 1) ? W1 : W2;
    const float* bias = (z == 0) ? b0 : (z == 1) ? b1 : b2;
    float* C          = (z == 0) ? C0 : (z == 1) ? C1 : C2;
    const int mode    = (z == 0) ? mode0 : (z == 1) ? mode1 : mode2;

    const int m0 = blockIdx.y * 128, n0 = blockIdx.x * 128;
    const int tid  = threadIdx.x;
    const int warp = tid >> 5, lane = tid & 31;
    const int wm = warp >> 2, wn = warp & 3;     // warp grid 2 x 4 (64x32 each)
    const int g  = lane >> 2, tg = lane & 3;

    const int lrow = tid >> 1, lkq = tid & 1;
    const float* Ap = A + (size_t)(m0 + lrow) * K + lkq * 16;
    const float* Wp = W + (size_t)(n0 + lrow) * K + lkq * 16;
    const int dsto = lrow * 36 + lkq * 16;

    float acc[4][4][4];
#pragma unroll
    for (int mt = 0; mt < 4; mt++)
#pragma unroll
        for (int nt = 0; nt < 4; nt++)
#pragma unroll
            for (int c = 0; c < 4; c++) acc[mt][nt][c] = 0.f;

    float4 ar[4], wr[4];
#pragma unroll
    for (int i = 0; i < 4; i++) {
        ar[i] = *(const float4*)(Ap + i * 4);
        wr[i] = *(const float4*)(Wp + i * 4);
    }
#pragma unroll
    for (int i = 0; i < 4; i++) {
        float4 c;
        c.x = tf32r(ar[i].x); c.y = tf32r(ar[i].y);
        c.z = tf32r(ar[i].z); c.w = tf32r(ar[i].w);
        *(float4*)(Asm + dsto + i * 4) = c;
        c.x = tf32r(wr[i].x); c.y = tf32r(wr[i].y);
        c.z = tf32r(wr[i].z); c.w = tf32r(wr[i].w);
        *(float4*)(Wsm + dsto + i * 4) = c;
    }
    __syncthreads();

    const int niter = K >> 5;
    int p = 0;
    for (int it = 0; it < niter; ++it) {
        if (it + 1 < niter) {
            const int ko = (it + 1) << 5;
#pragma unroll
            for (int i = 0; i < 4; i++) {
                ar[i] = *(const float4*)(Ap + ko + i * 4);
                wr[i] = *(const float4*)(Wp + ko + i * 4);
            }
        }
        const float* ab = Asm + p * (128 * 36);
        const float* wb = Wsm + p * (128 * 36);
#pragma unroll
        for (int kb = 0; kb < 4; kb++) {
            const int kk = kb * 8 + tg;
            unsigned a[4][4], b[4][2];
#pragma unroll
            for (int mt = 0; mt < 4; mt++) {
                const int rm = wm * 64 + mt * 16 + g;
                a[mt][0] = __float_as_uint(ab[rm * 36 + kk]);
                a[mt][1] = __float_as_uint(ab[(rm + 8) * 36 + kk]);
                a[mt][2] = __float_as_uint(ab[rm * 36 + kk + 4]);
                a[mt][3] = __float_as_uint(ab[(rm + 8) * 36 + kk + 4]);
            }
#pragma unroll
            for (int nt = 0; nt < 4; nt++) {
                const int rn = wn * 32 + nt * 8 + g;
                b[nt][0] = __float_as_uint(wb[rn * 36 + kk]);
                b[nt][1] = __float_as_uint(wb[rn * 36 + kk + 4]);
            }
#pragma unroll
            for (int mt = 0; mt < 4; mt++)
#pragma unroll
                for (int nt = 0; nt < 4; nt++)
                    mma_tf32(acc[mt][nt], a[mt], b[nt]);
        }
        if (it + 1 < niter) {
            float* ad = Asm + (p ^ 1) * (128 * 36) + dsto;
            float* wd = Wsm + (p ^ 1) * (128 * 36) + dsto;
#pragma unroll
            for (int i = 0; i < 4; i++) {
                float4 c;
                c.x = tf32r(ar[i].x); c.y = tf32r(ar[i].y);
                c.z = tf32r(ar[i].z); c.w = tf32r(ar[i].w);
                *(float4*)(ad + i * 4) = c;
                c.x = tf32r(wr[i].x); c.y = tf32r(wr[i].y);
                c.z = tf32r(wr[i].z); c.w = tf32r(wr[i].w);
                *(float4*)(wd + i * 4) = c;
            }
        }
        __syncthreads();
        p ^= 1;
    }

#pragma unroll
    for (int mt = 0; mt < 4; mt++) {
#pragma unroll
        for (int nt = 0; nt < 4; nt++) {
            const int row0 = m0 + wm * 64 + mt * 16 + g;
            const int col0 = n0 + wn * 32 + nt * 8 + 2 * tg;
            store_elem(C, bias, masks, mode, N, row0,     col0,     acc[mt][nt][0]);
            store_elem(C, bias, masks, mode, N, row0,     col0 + 1, acc[mt][nt][1]);
            store_elem(C, bias, masks, mode, N, row0 + 8, col0,     acc[mt][nt][2]);
            store_elem(C, bias, masks, mode, N, row0 + 8, col0 + 1, acc[mt][nt][3]);
        }
    }
}

// ------------------------- fused attention (scores+softmax+PV) --------------
#define ATTN_SMEM_FLOATS (128*68 + 64*68 + 64*68 + 256 + 256)
__global__ void __launch_bounds__(256) attn_kernel(
    const float* __restrict__ Q, const float* __restrict__ K,
    const float* __restrict__ VT, float* __restrict__ CC,
    const int* __restrict__ lengths)
{
    extern __shared__ float sm[];
    float* Ps   = sm;
    float* Ks   = sm + 128 * 68;
    float* Vs   = Ks + 64 * 68;
    float* smax = Vs + 64 * 68;
    float* ssum = smax + 256;

    const int qt = blockIdx.x, z = blockIdx.y;
    const int b = z >> 3, h = z & 7;
    const int q0 = qt * 128;
    const int len = __ldg(lengths + b);
    const int tid = threadIdx.x;
    const int warp = tid >> 5, lane = tid & 31;
    const int wm = warp >> 1, wn = warp & 1;
    const int g = lane >> 2, tg = lane & 3;

    const float* Qb = Q + ((size_t)z * NS + q0) * NDK;
#pragma unroll
    for (int i = 0; i < 8; i++) {
        const int idx = tid * 32 + i * 4;
        const int r = idx >> 6, c = idx & 63;
        float4 v = *(const float4*)(Qb + r * 64 + c);
        float* d = &Ps[r * 68 + c];
        d[0] = tf32r(v.x); d[1] = tf32r(v.y); d[2] = tf32r(v.z); d[3] = tf32r(v.w);
    }
    __syncthreads();

    unsigned qf[2][8][4];
#pragma unroll
    for (int mt = 0; mt < 2; mt++)
#pragma unroll
        for (int kb = 0; kb < 8; kb++) {
            const int rm = wm * 32 + mt * 16 + g;
            const int kk = kb * 8 + tg;
            qf[mt][kb][0] = __float_as_uint(Ps[rm * 68 + kk]);
            qf[mt][kb][1] = __float_as_uint(Ps[(rm + 8) * 68 + kk]);
            qf[mt][kb][2] = __float_as_uint(Ps[rm * 68 + kk + 4]);
            qf[mt][kb][3] = __float_as_uint(Ps[(rm + 8) * 68 + kk + 4]);
        }

    float oacc[2][4][4];
#pragma unroll
    for (int mt = 0; mt < 2; mt++)
#pragma unroll
        for (int nt = 0; nt < 4; nt++)
#pragma unroll
            for (int c = 0; c < 4; c++) oacc[mt][nt][c] = 0.f;
    float mrow[2][2] = {{-1e30f, -1e30f}, {-1e30f, -1e30f}};
    float srow[2][2] = {{0.f, 0.f}, {0.f, 0.f}};

    const int nch = (len + 63) >> 6;
    for (int kc = 0; kc < nch; kc++) {
        __syncthreads();
        const float* Kb = K + ((size_t)z * NS + kc * 64) * NDK;
#pragma unroll
        for (int i = 0; i < 4; i++) {
            const int idx = tid * 16 + i * 4;
            const int r = idx >> 6, c = idx & 63;
            float4 kv = *(const float4*)(Kb + r * 64 + c);
            float* dk = &Ks[r * 68 + c];
            dk[0] = tf32r(kv.x); dk[1] = tf32r(kv.y); dk[2] = tf32r(kv.z); dk[3] = tf32r(kv.w);
            float4 vv = *(const float4*)(VT + ((size_t)z * 64 + r) * NS + kc * 64 + c);
            float* dv = &Vs[r * 68 + c];
            dv[0] = tf32r(vv.x); dv[1] = tf32r(vv.y); dv[2] = tf32r(vv.z); dv[3] = tf32r(vv.w);
        }
        __syncthreads();
        float sacc[2][4][4];
#pragma unroll
        for (int mt = 0; mt < 2; mt++)
#pragma unroll
            for (int nt = 0; nt < 4; nt++)
#pragma unroll
                for (int c = 0; c < 4; c++) sacc[mt][nt][c] = 0.f;
#pragma unroll
        for (int kb = 0; kb < 8; kb++) {
            const int kk = kb * 8 + tg;
            unsigned bf[4][2];
#pragma unroll
            for (int nt = 0; nt < 4; nt++) {
                const int rn = wn * 32 + nt * 8 + g;
                bf[nt][0] = __float_as_uint(Ks[rn * 68 + kk]);
                bf[nt][1] = __float_as_uint(Ks[rn * 68 + kk + 4]);
            }
#pragma unroll
            for (int mt = 0; mt < 2; mt++)
#pragma unroll
                for (int nt = 0; nt < 4; nt++)
                    mma_tf32(sacc[mt][nt], qf[mt][kb], bf[nt]);
        }
#pragma unroll
        for (int mt = 0; mt < 2; mt++)
#pragma unroll
            for (int nt = 0; nt < 4; nt++) {
                const int col = kc * 64 + wn * 32 + nt * 8 + 2 * tg;
                const bool ok0 = col < len, ok1 = col + 1 < len;
                sacc[mt][nt][0] = ok0 ? sacc[mt][nt][0] * 0.125f : -1e30f;
                sacc[mt][nt][1] = ok1 ? sacc[mt][nt][1] * 0.125f : -1e30f;
                sacc[mt][nt][2] = ok0 ? sacc[mt][nt][2] * 0.125f : -1e30f;
                sacc[mt][nt][3] = ok1 ? sacc[mt][nt][3] * 0.125f : -1e30f;
            }
        float cmax[2][2] = {{-1e30f, -1e30f}, {-1e30f, -1e30f}};
#pragma unroll
        for (int mt = 0; mt < 2; mt++)
#pragma unroll
            for (int nt = 0; nt < 4; nt++) {
                cmax[mt][0] = fmaxf(cmax[mt][0], fmaxf(sacc[mt][nt][0], sacc[mt][nt][1]));
                cmax[mt][1] = fmaxf(cmax[mt][1], fmaxf(sacc[mt][nt][2], sacc[mt][nt][3]));
            }
#pragma unroll
        for (int off = 1; off < 4; off <<= 1)
#pragma unroll
            for (int mt = 0; mt < 2; mt++) {
                cmax[mt][0] = fmaxf(cmax[mt][0], __shfl_xor_sync(~0u, cmax[mt][0], off));
                cmax[mt][1] = fmaxf(cmax[mt][1], __shfl_xor_sync(~0u, cmax[mt][1], off));
            }
        if (tg == 0) {
#pragma unroll
            for (int mt = 0; mt < 2; mt++) {
                smax[wn * 128 + wm * 32 + mt * 16 + g]     = cmax[mt][0];
                smax[wn * 128 + wm * 32 + mt * 16 + 8 + g] = cmax[mt][1];
            }
        }
        __syncthreads();
        float alpha[2][2], csum[2][2] = {{0.f, 0.f}, {0.f, 0.f}};
#pragma unroll
        for (int mt = 0; mt < 2; mt++)
#pragma unroll
            for (int hh = 0; hh < 2; hh++) {
                const int row = wm * 32 + mt * 16 + hh * 8 + g;
                const float cm = fmaxf(smax[row], smax[128 + row]);
                const float mn = fmaxf(mrow[mt][hh], cm);
                alpha[mt][hh] = __expf(mrow[mt][hh] - mn);
                mrow[mt][hh] = mn;
            }
#pragma unroll
        for (int mt = 0; mt < 2; mt++)
#pragma unroll
            for (int nt = 0; nt < 4; nt++) {
                sacc[mt][nt][0] = __expf(sacc[mt][nt][0] - mrow[mt][0]);
                sacc[mt][nt][1] = __expf(sacc[mt][nt][1] - mrow[mt][0]);
                sacc[mt][nt][2] = __expf(sacc[mt][nt][2] - mrow[mt][1]);
                sacc[mt][nt][3] = __expf(sacc[mt][nt][3] - mrow[mt][1]);
                csum[mt][0] += sacc[mt][nt][0] + sacc[mt][nt][1];
                csum[mt][1] += sacc[mt][nt][2] + sacc[mt][nt][3];
            }
#pragma unroll
        for (int off = 1; off < 4; off <<= 1)
#pragma unroll
            for (int mt = 0; mt < 2; mt++) {
                csum[mt][0] += __shfl_xor_sync(~0u, csum[mt][0], off);
                csum[mt][1] += __shfl_xor_sync(~0u, csum[mt][1], off);
            }
        if (tg == 0) {
#pragma unroll
            for (int mt = 0; mt < 2; mt++) {
                ssum[wn * 128 + wm * 32 + mt * 16 + g]     = csum[mt][0];
                ssum[wn * 128 + wm * 32 + mt * 16 + 8 + g] = csum[mt][1];
            }
        }
#pragma unroll
        for (int mt = 0; mt < 2; mt++)
#pragma unroll
            for (int nt = 0; nt < 4; nt++) {
                oacc[mt][nt][0] *= alpha[mt][0];
                oacc[mt][nt][1] *= alpha[mt][0];
                oacc[mt][nt][2] *= alpha[mt][1];
                oacc[mt][nt][3] *= alpha[mt][1];
                const int r0 = wm * 32 + mt * 16 + g;
                const int col = wn * 32 + nt * 8 + 2 * tg;
                Ps[r0 * 68 + col]           = tf32r(sacc[mt][nt][0]);
                Ps[r0 * 68 + col + 1]       = tf32r(sacc[mt][nt][1]);
                Ps[(r0 + 8) * 68 + col]     = tf32r(sacc[mt][nt][2]);
                Ps[(r0 + 8) * 68 + col + 1] = tf32r(sacc[mt][nt][3]);
            }
        __syncthreads();
#pragma unroll
        for (int mt = 0; mt < 2; mt++)
#pragma unroll
            for (int hh = 0; hh < 2; hh++) {
                const int row = wm * 32 + mt * 16 + hh * 8 + g;
                srow[mt][hh] = srow[mt][hh] * alpha[mt][hh] + ssum[row] + ssum[128 + row];
            }
#pragma unroll
        for (int kb = 0; kb < 8; kb++) {
            const int kk = kb * 8 + tg;
            unsigned af[2][4], bf[4][2];
#pragma unroll
            for (int mt = 0; mt < 2; mt++) {
                const int rm = wm * 32 + mt * 16 + g;
                af[mt][0] = __float_as_uint(Ps[rm * 68 + kk]);
                af[mt][1] = __float_as_uint(Ps[(rm + 8) * 68 + kk]);
                af[mt][2] = __float_as_uint(Ps[rm * 68 + kk + 4]);
                af[mt][3] = __float_as_uint(Ps[(rm + 8) * 68 + kk + 4]);
            }
#pragma unroll
            for (int nt = 0; nt < 4; nt++) {
                const int rn = wn * 32 + nt * 8 + g;
                bf[nt][0] = __float_as_uint(Vs[rn * 68 + kk]);
                bf[nt][1] = __float_as_uint(Vs[rn * 68 + kk + 4]);
            }
#pragma unroll
            for (int mt = 0; mt < 2; mt++)
#pragma unroll
                for (int nt = 0; nt < 4; nt++)
                    mma_tf32(oacc[mt][nt], af[mt], bf[nt]);
        }
    }
#pragma unroll
    for (int mt = 0; mt < 2; mt++) {
        const float i0 = 1.f / srow[mt][0];
        const float i1 = 1.f / srow[mt][1];
        const int r0 = q0 + wm * 32 + mt * 16 + g;
        const bool ok0 = r0 < len, ok1 = (r0 + 8) < len;
#pragma unroll
        for (int nt = 0; nt < 4; nt++) {
            const int col = h * 64 + wn * 32 + nt * 8 + 2 * tg;
            float2 v0, v1;
            v0.x = ok0 ? oacc[mt][nt][0] * i0 : 0.f;
            v0.y = ok0 ? oacc[mt][nt][1] * i0 : 0.f;
            v1.x = ok1 ? oacc[mt][nt][2] * i1 : 0.f;
            v1.y = ok1 ? oacc[mt][nt][3] * i1 : 0.f;
            *(float2*)&CC[((size_t)b * NS + r0) * ND + col]     = v0;
            *(float2*)&CC[((size_t)b * NS + r0 + 8) * ND + col] = v1;
        }
    }
}

// ------------------------- flag reset -------------------------
__global__ void reset_kernel() {
    g_flag[blockIdx.x * 256 + threadIdx.x] = 0u;
}

// ------------------------- persistent GRU (fused acquire+load consumer) -----
// 128 blocks = dir(2) x batchgroup(8 of 4 batches) x jchunk(8 of 32 j).
// 384 threads = rg(48, 2 gate-rows) x ks(8, 32-k slice); weights in registers.
// Producer release (unchanged, proven): st.cg h -> __syncthreads -> tid0:
// __threadfence + flag store (8 block-grain flags/group, own 128B lines).
// Consumer (NEW): each of 256 threads acquire-polls the one flag of the rank
// producing its 16B, then ld.cg.v4 immediately — early ranks' data loads
// overlap late ranks' waits; one barrier + one hop removed per step.
__global__ void __launch_bounds__(384, 1) gru_kernel(
    const float* __restrict__ whf, const float* __restrict__ whb,
    const float* __restrict__ bhf, const float* __restrict__ bhb,
    const int* __restrict__ masks, float* __restrict__ hid_out)
{
    __shared__ float sh_h[1024];
    __shared__ float sh_gate[384];

    const int bid = blockIdx.x;
    const int dir = bid >> 6;
    const int rem = bid & 63;
    const int bg  = rem >> 3;
    const int jc  = rem & 7;
    const int grp = dir * 8 + bg;
    const int tid = threadIdx.x;
    const int rg  = tid >> 3;
    const int ks  = tid & 7;
    const int row0 = rg * 2, row1 = rg * 2 + 1;
    const int G0 = (row0 >> 5) * 256 + jc * 32 + (row0 & 31);
    const int G1 = (row1 >> 5) * 256 + jc * 32 + (row1 & 31);

    const float* wh = dir ? whb : whf;
    const float* bh = dir ? bhb : bhf;
    const float bh0 = bh[G0], bh1 = bh[G1];

    unsigned long long wp0[16], wp1[16];
    {
        const float* w0s = wh + (long)G0 * NH2 + ks * 32;
        const float* w1s = wh + (long)G1 * NH2 + ks * 32;
#pragma unroll
        for (int i = 0; i < 16; i++) {
            wp0[i] = pack2(w0s[2 * i], w0s[2 * i + 1]);
            wp1[i] = pack2(w1s[2 * i], w1s[2 * i + 1]);
        }
    }

    const int ju = tid & 31, bu = tid >> 5;
    const int jglob = jc * 32 + ju;
    const int bglob = bg * 4 + bu;
    const float* xgp = g_xg + ((size_t)dir * NB + bglob) * NS * NG3;
    float* hxg = g_hx + grp * 2048;
    unsigned* myflag = &g_flag[(grp * 8 + jc) * 32];

    // consumer precompute (tid < 256): floats 4*tid..4*tid+3 of the h buffer
    const int cb = tid >> 6, cc0 = tid & 63;           // batch, chunk-in-batch
    const int crank = cc0 >> 3;                        // producer rank of this chunk
    const unsigned* cflag = &g_flag[(grp * 8 + crank) * 32];
    const int csw = ((cc0 >> 3) << 3) | ((cc0 & 7) ^ (cc0 >> 3));
    float* shdst = &sh_h[cb * 256 + csw * 4];

    for (int i = tid; i < 1024; i += 384) sh_h[i] = 0.f;
    float hreg = 0.f;
    __syncthreads();

    for (int t = 0; t < NS; t++) {
        const int s = dir ? (NS - 1 - t) : t;
        float xr = 0.f, xz = 0.f, xn = 0.f;
        int mk = 0;
        if (tid < 128) {
            const float* xrow = xgp + (size_t)s * NG3;
            xr = __ldg(xrow + jglob);
            xz = __ldg(xrow + NH2 + jglob);
            xn = __ldg(xrow + 2 * NH2 + jglob);
            mk = __ldg(masks + bglob * NS + s);
        }
        if (t > 0) {
            if (tid < 256) {
                unsigned v;
                do {
                    asm volatile("ld.global.acquire.gpu.u32 %0, [%1];"
                                 : "=r"(v) : "l"(cflag) : "memory");
                } while (v < (unsigned)t);
                const float* src = hxg + ((t - 1) & 1) * 1024 + tid * 4;
                float4 hv4;
                asm volatile("ld.global.cg.v4.f32 {%0,%1,%2,%3}, [%4];"
                             : "=f"(hv4.x), "=f"(hv4.y), "=f"(hv4.z), "=f"(hv4.w)
                             : "l"(src) : "memory");
                *(float4*)shdst = hv4;
            }
            __syncthreads();
        }
        unsigned long long a0[4] = {0ull, 0ull, 0ull, 0ull};
        unsigned long long a1[4] = {0ull, 0ull, 0ull, 0ull};
#pragma unroll
        for (int i = 0; i < 8; i++) {
            const int coff = (((ks << 3) | (i ^ ks)) << 2);
#pragma unroll
            for (int b = 0; b < 4; b++) {
                ulonglong2 hv = *(const ulonglong2*)(sh_h + b * 256 + coff);
                a0[b] = fma2(wp0[2 * i],     hv.x, a0[b]);
                a0[b] = fma2(wp0[2 * i + 1], hv.y, a0[b]);
                a1[b] = fma2(wp1[2 * i],     hv.x, a1[b]);
                a1[b] = fma2(wp1[2 * i + 1], hv.y, a1[b]);
            }
        }
        float v0[4], v1[4];
#pragma unroll
        for (int b = 0; b < 4; b++) {
            float lo, hi;
            unpack2(a0[b], lo, hi); v0[b] = lo + hi;
            unpack2(a1[b], lo, hi); v1[b] = lo + hi;
        }
#pragma unroll
        for (int off = 1; off < 8; off <<= 1) {
#pragma unroll
            for (int b = 0; b < 4; b++) {
                v0[b] += __shfl_xor_sync(~0u, v0[b], off);
                v1[b] += __shfl_xor_sync(~0u, v1[b], off);
            }
        }
        if (ks == 0) {
            float4 f0 = make_float4(v0[0] + bh0, v0[1] + bh0, v0[2] + bh0, v0[3] + bh0);
            float4 f1 = make_float4(v1[0] + bh1, v1[1] + bh1, v1[2] + bh1, v1[3] + bh1);
            *(float4*)&sh_gate[rg * 8]     = f0;
            *(float4*)&sh_gate[rg * 8 + 4] = f1;
        }
        __syncthreads();
        if (tid < 128) {
            const float hgr = sh_gate[ju * 4 + bu];
            const float hgz = sh_gate[(32 + ju) * 4 + bu];
            const float hgn = sh_gate[(64 + ju) * 4 + bu];
            const float rr = 1.f / (1.f + __expf(-(xr + hgr)));
            const float zz = 1.f / (1.f + __expf(-(xz + hgz)));
            const float na = xn + rr * hgn;
            const float nn = 2.f / (1.f + __expf(-2.f * na)) - 1.f;
            const float hnew = (1.f - zz) * nn + zz * hreg;
            hreg = mk ? hnew : hreg;
            g_gru[((size_t)bglob * NS + s) * ND + dir * NH2 + jglob] = mk ? hreg : 0.f;
            if (t == NS - 1) {
                hid_out[bglob * ND + dir * NH2 + jglob] = hreg;
            } else {
                __stcg(hxg + (t & 1) * 1024 + bu * 256 + jglob, hreg);
            }
        }
        if (t < NS - 1) {
            __syncthreads();
            if (tid == 0) {
                __threadfence();
                unsigned nv = (unsigned)(t + 1);
                asm volatile("st.global.cg.u32 [%0], %1;"
                             :: "l"(myflag), "r"(nv) : "memory");
            }
        }
    }
}

// ------------------------- layernorm (optionally fused residual) ------------
__global__ void __launch_bounds__(128) ln_kernel(
    const float* __restrict__ x, const float* __restrict__ y,
    const float* __restrict__ gam, const float* __restrict__ bet,
    float* __restrict__ out)
{
    __shared__ float red[8];
    const int row = blockIdx.x;
    const int tid = threadIdx.x;
    float4 v = *(const float4*)(x + (size_t)row * ND + tid * 4);
    if (y) {
        float4 w = *(const float4*)(y + (size_t)row * ND + tid * 4);
        v.x += w.x; v.y += w.y; v.z += w.z; v.w += w.w;
    }
    float s1 = v.x + v.y + v.z + v.w;
    float s2 = v.x * v.x + v.y * v.y + v.z * v.z + v.w * v.w;
#pragma unroll
    for (int o = 16; o; o >>= 1) {
        s1 += __shfl_xor_sync(~0u, s1, o);
        s2 += __shfl_xor_sync(~0u, s2, o);
    }
    const int wid = tid >> 5;
    if ((tid & 31) == 0) { red[wid] = s1; red[wid + 4] = s2; }
    __syncthreads();
    s1 = red[0] + red[1] + red[2] + red[3];
    s2 = red[4] + red[5] + red[6] + red[7];
    const float mu = s1 * (1.f / ND);
    const float var = s2 * (1.f / ND) - mu * mu;
    const float rs = rsqrtf(var + 1e-5f);
    const float4 gv = *(const float4*)(gam + tid * 4);
    const float4 bv = *(const float4*)(bet + tid * 4);
    float4 o4;
    o4.x = (v.x - mu) * rs * gv.x + bv.x;
    o4.y = (v.y - mu) * rs * gv.y + bv.y;
    o4.z = (v.z - mu) * rs * gv.z + bv.z;
    o4.w = (v.w - mu) * rs * gv.w + bv.w;
    *(float4*)(out + (size_t)row * ND + tid * 4) = o4;
}

// ------------------------- launch -------------------------
extern "C" void kernel_launch(void* const* d_in, const int* in_sizes, int n_in,
                              void* d_out, int out_size)
{
    const float* splits = (const float*)d_in[0];
    const float* w_ih_f = (const float*)d_in[1];
    const float* w_hh_f = (const float*)d_in[2];
    const float* b_ih_f = (const float*)d_in[3];
    const float* b_hh_f = (const float*)d_in[4];
    const float* w_ih_b = (const float*)d_in[5];
    const float* w_hh_b = (const float*)d_in[6];
    const float* b_ih_b = (const float*)d_in[7];
    const float* b_hh_b = (const float*)d_in[8];
    const float* ln1_g  = (const float*)d_in[9];
    const float* ln1_b  = (const float*)d_in[10];
    const float* wq = (const float*)d_in[11];
    const float* bq = (const float*)d_in[12];
    const float* wk = (const float*)d_in[13];
    const float* bk = (const float*)d_in[14];
    const float* wv = (const float*)d_in[15];
    const float* bv = (const float*)d_in[16];
    const float* wo = (const float*)d_in[17];
    const float* bo = (const float*)d_in[18];
    const float* ln2_g = (const float*)d_in[19];
    const float* ln2_b = (const float*)d_in[20];
    const int* lengths = (const int*)d_in[21];
    const int* masks   = (const int*)d_in[22];
    float* out = (float*)d_out;

    float *xg, *gru, *ln1, *q, *k, *vt, *cc, *oo;
    cudaGetSymbolAddress((void**)&xg,  g_xg);
    cudaGetSymbolAddress((void**)&gru, g_gru);
    cudaGetSymbolAddress((void**)&ln1, g_ln1);
    cudaGetSymbolAddress((void**)&q,   g_q);
    cudaGetSymbolAddress((void**)&k,   g_k);
    cudaGetSymbolAddress((void**)&vt,  g_vt);
    cudaGetSymbolAddress((void**)&cc,  g_cc);
    cudaGetSymbolAddress((void**)&oo,  g_o);

    const int M = NB * NS;  // 16384
    const int ATTN_SMEM = ATTN_SMEM_FLOATS * 4;
    cudaFuncSetAttribute(attn_kernel, cudaFuncAttributeMaxDynamicSharedMemorySize, ATTN_SMEM);
    cudaFuncSetAttribute(gemm3, cudaFuncAttributeMaxDynamicSharedMemorySize, G3_SMEM);

    // GRU input projections — one launch, z = dir
    gemm3<<<dim3(6, 128, 2), 256, G3_SMEM>>>(
        splits, w_ih_f, w_ih_b, nullptr, b_ih_f, b_ih_b, nullptr,
        xg, xg + (size_t)M * NG3, nullptr, 0, 0, 0,
        M, NG3, ND, nullptr);
    // GRU recurrence (persistent, per-rank flag sync through L2)
    reset_kernel<<<16, 256>>>();
    gru_kernel<<<128, 384>>>(w_hh_f, w_hh_b, b_hh_f, b_hh_b, masks,
                             out + (size_t)NB * NS * ND);
    // LN1
    ln_kernel<<<M, 128>>>(gru, nullptr, ln1_g, ln1_b, ln1);
    // Q/K/V projections — one launch, z = {q, k, v}
    gemm3<<<dim3(4, 128, 3), 256, G3_SMEM>>>(
        ln1, wq, wk, wv, bq, bk, bv,
        q, k, vt, 1, 1, 2,
        M, ND, ND, nullptr);
    // fused attention: scores + masked online softmax + PV -> concat
    attn_kernel<<<dim3(4, 256), 256, ATTN_SMEM>>>(q, k, vt, cc, lengths);
    // out projection + row mask
    gemm3<<<dim3(4, 128, 1), 256, G3_SMEM>>>(
        cc, wo, nullptr, nullptr, bo, nullptr, nullptr,
        oo, nullptr, nullptr, 5, 5, 5,
        M, ND, ND, masks);
    // residual + LN2 -> final outputs
    ln_kernel<<<M, 128>>>(ln1, oo, ln2_g, ln2_b, out);
}

// round 16
// speedup vs baseline: 1.0910x; 1.0910x over previous
#include <cuda_runtime.h>
#include <cstdint>
#include <cstddef>

#define NB   32
#define NS   512
#define ND   512
#define NH2  256
#define NG3  768
#define NDK  64

// ------------------------- scratch (device globals) -------------------------
__device__ float g_xg[(size_t)2 * NB * NS * NG3];   // gate preactivations, per dir
__device__ float g_gru[(size_t)NB * NS * ND];       // concat GRU outputs
__device__ float g_ln1[(size_t)NB * NS * ND];       // ln1("outputs")
__device__ float g_q [(size_t)NB * 8 * NS * NDK];   // (b,h,s,d)
__device__ float g_k [(size_t)NB * 8 * NS * NDK];   // (b,h,s,d)
__device__ float g_vt[(size_t)NB * 8 * NDK * NS];   // (b,h,d,s)
__device__ float g_cc[(size_t)NB * NS * ND];        // attn concat
__device__ float g_o [(size_t)NB * NS * ND];        // out projection
__device__ float g_hx[16 * 2048];                   // h exchange (16 groups x 2 bufs x 1024)
__device__ unsigned g_flag[16 * 8 * 32];            // per (group,rank) step flag, 1 per 128B line

// ------------------------- helpers -------------------------
__device__ __forceinline__ unsigned long long fma2(unsigned long long a,
                                                   unsigned long long b,
                                                   unsigned long long c) {
    unsigned long long d;
    asm("fma.rn.f32x2 %0, %1, %2, %3;" : "=l"(d) : "l"(a), "l"(b), "l"(c));
    return d;
}
__device__ __forceinline__ unsigned long long pack2(float x, float y) {
    unsigned long long d;
    asm("mov.b64 %0, {%1, %2};" : "=l"(d) : "f"(x), "f"(y));
    return d;
}
__device__ __forceinline__ void unpack2(unsigned long long v, float& x, float& y) {
    asm("mov.b64 {%0, %1}, %2;" : "=f"(x), "=f"(y) : "l"(v));
}
__device__ __forceinline__ float tf32r(float f) {
    unsigned u;
    asm("cvt.rna.tf32.f32 %0, %1;" : "=r"(u) : "f"(f));
    return __uint_as_float(u);
}
__device__ __forceinline__ void mma_tf32(float* acc, const unsigned* a, const unsigned* b) {
    asm volatile(
        "mma.sync.aligned.m16n8k8.row.col.f32.tf32.tf32.f32 "
        "{%0,%1,%2,%3}, {%4,%5,%6,%7}, {%8,%9}, {%0,%1,%2,%3};"
        : "+f"(acc[0]), "+f"(acc[1]), "+f"(acc[2]), "+f"(acc[3])
        : "r"(a[0]), "r"(a[1]), "r"(a[2]), "r"(a[3]),
          "r"(b[0]), "r"(b[1]));
}

// ------------------------- epilogue store -------------------------
// 0: +bias   1: +bias, scatter (b,h,s,d)   2: +bias, scatter (b,h,d,s)
// 5: +bias, *rowmask(masks)
__device__ __forceinline__ void store_elem(float* C, const float* bias,
                                           const int* masks, int mode,
                                           int N, int mrow, int nc, float v) {
    if (mode == 0) {
        C[(size_t)mrow * N + nc] = v + bias[nc];
    } else if (mode == 1) {
        int b = mrow >> 9, s = mrow & 511, h = nc >> 6, d = nc & 63;
        C[(((size_t)(b * 8 + h) * NS + s)) * NDK + d] = v + bias[nc];
    } else if (mode == 2) {
        int b = mrow >> 9, s = mrow & 511, h = nc >> 6, d = nc & 63;
        C[((size_t)(b * 8 + h) * NDK + d) * NS + s] = v + bias[nc];
    } else {
        C[(size_t)mrow * N + nc] = masks[mrow] ? (v + bias[nc]) : 0.f;
    }
}

// ------------------------- tf32 TN GEMM, double-buffered, up to 3 ops/z -----
// C = epi(A[M,K] @ W[N,K]^T). Requires M%128==0, N%128==0, K%32==0.
// 128x128x32 tile, 2-stage smem pipeline, 1 syncthreads per K-chunk.
// Prefix-mask tile skip: masks is a PREFIX mask over M rows; if the first row
// of this 128-row tile is masked, the whole tile is immaterial downstream
// (modes 0/1/2: outputs never observed; mode 5: output is exactly zero).
#define G3_SMEM (2 * 2 * 128 * 36 * 4)
__global__ void __launch_bounds__(256) gemm3(
    const float* __restrict__ A,
    const float* __restrict__ W0, const float* __restrict__ W1, const float* __restrict__ W2,
    const float* __restrict__ b0, const float* __restrict__ b1, const float* __restrict__ b2,
    float* __restrict__ C0, float* __restrict__ C1, float* __restrict__ C2,
    int mode0, int mode1, int mode2,
    int M, int N, int K, const int* __restrict__ masks)
{
    extern __shared__ float smg[];
    float* Asm = smg;                 // [2][128][36]
    float* Wsm = smg + 2 * 128 * 36;  // [2][128][36]

    const int z = blockIdx.z;
    const float* W    = (z == 0) ? W0 : (z == 1) ? W1 : W2;
    const float* bias = (z == 0) ? b0 : (z == 1) ? b1 : b2;
    float* C          = (z == 0) ? C0 : (z == 1) ? C1 : C2;
    const int mode    = (z == 0) ? mode0 : (z == 1) ? mode1 : mode2;

    const int m0 = blockIdx.y * 128, n0 = blockIdx.x * 128;
    const int tid  = threadIdx.x;

    // ---- prefix-mask tile skip ----
    if (masks && __ldg(masks + m0) == 0) {
        if (mode == 5) {  // output must be exactly zero
            for (int i = tid; i < 128 * 32; i += 256) {
                const int r = i >> 5, c4 = i & 31;
                *(float4*)&C[(size_t)(m0 + r) * N + n0 + c4 * 4] =
                    make_float4(0.f, 0.f, 0.f, 0.f);
            }
        }
        return;  // modes 0/1/2: rows never observed downstream
    }

    const int warp = tid >> 5, lane = tid & 31;
    const int wm = warp >> 2, wn = warp & 3;     // warp grid 2 x 4 (64x32 each)
    const int g  = lane >> 2, tg = lane & 3;

    const int lrow = tid >> 1, lkq = tid & 1;
    const float* Ap = A + (size_t)(m0 + lrow) * K + lkq * 16;
    const float* Wp = W + (size_t)(n0 + lrow) * K + lkq * 16;
    const int dsto = lrow * 36 + lkq * 16;

    float acc[4][4][4];
#pragma unroll
    for (int mt = 0; mt < 4; mt++)
#pragma unroll
        for (int nt = 0; nt < 4; nt++)
#pragma unroll
            for (int c = 0; c < 4; c++) acc[mt][nt][c] = 0.f;

    float4 ar[4], wr[4];
#pragma unroll
    for (int i = 0; i < 4; i++) {
        ar[i] = *(const float4*)(Ap + i * 4);
        wr[i] = *(const float4*)(Wp + i * 4);
    }
#pragma unroll
    for (int i = 0; i < 4; i++) {
        float4 c;
        c.x = tf32r(ar[i].x); c.y = tf32r(ar[i].y);
        c.z = tf32r(ar[i].z); c.w = tf32r(ar[i].w);
        *(float4*)(Asm + dsto + i * 4) = c;
        c.x = tf32r(wr[i].x); c.y = tf32r(wr[i].y);
        c.z = tf32r(wr[i].z); c.w = tf32r(wr[i].w);
        *(float4*)(Wsm + dsto + i * 4) = c;
    }
    __syncthreads();

    const int niter = K >> 5;
    int p = 0;
    for (int it = 0; it < niter; ++it) {
        if (it + 1 < niter) {
            const int ko = (it + 1) << 5;
#pragma unroll
            for (int i = 0; i < 4; i++) {
                ar[i] = *(const float4*)(Ap + ko + i * 4);
                wr[i] = *(const float4*)(Wp + ko + i * 4);
            }
        }
        const float* ab = Asm + p * (128 * 36);
        const float* wb = Wsm + p * (128 * 36);
#pragma unroll
        for (int kb = 0; kb < 4; kb++) {
            const int kk = kb * 8 + tg;
            unsigned a[4][4], b[4][2];
#pragma unroll
            for (int mt = 0; mt < 4; mt++) {
                const int rm = wm * 64 + mt * 16 + g;
                a[mt][0] = __float_as_uint(ab[rm * 36 + kk]);
                a[mt][1] = __float_as_uint(ab[(rm + 8) * 36 + kk]);
                a[mt][2] = __float_as_uint(ab[rm * 36 + kk + 4]);
                a[mt][3] = __float_as_uint(ab[(rm + 8) * 36 + kk + 4]);
            }
#pragma unroll
            for (int nt = 0; nt < 4; nt++) {
                const int rn = wn * 32 + nt * 8 + g;
                b[nt][0] = __float_as_uint(wb[rn * 36 + kk]);
                b[nt][1] = __float_as_uint(wb[rn * 36 + kk + 4]);
            }
#pragma unroll
            for (int mt = 0; mt < 4; mt++)
#pragma unroll
                for (int nt = 0; nt < 4; nt++)
                    mma_tf32(acc[mt][nt], a[mt], b[nt]);
        }
        if (it + 1 < niter) {
            float* ad = Asm + (p ^ 1) * (128 * 36) + dsto;
            float* wd = Wsm + (p ^ 1) * (128 * 36) + dsto;
#pragma unroll
            for (int i = 0; i < 4; i++) {
                float4 c;
                c.x = tf32r(ar[i].x); c.y = tf32r(ar[i].y);
                c.z = tf32r(ar[i].z); c.w = tf32r(ar[i].w);
                *(float4*)(ad + i * 4) = c;
                c.x = tf32r(wr[i].x); c.y = tf32r(wr[i].y);
                c.z = tf32r(wr[i].z); c.w = tf32r(wr[i].w);
                *(float4*)(wd + i * 4) = c;
            }
        }
        __syncthreads();
        p ^= 1;
    }

#pragma unroll
    for (int mt = 0; mt < 4; mt++) {
#pragma unroll
        for (int nt = 0; nt < 4; nt++) {
            const int row0 = m0 + wm * 64 + mt * 16 + g;
            const int col0 = n0 + wn * 32 + nt * 8 + 2 * tg;
            store_elem(C, bias, masks, mode, N, row0,     col0,     acc[mt][nt][0]);
            store_elem(C, bias, masks, mode, N, row0,     col0 + 1, acc[mt][nt][1]);
            store_elem(C, bias, masks, mode, N, row0 + 8, col0,     acc[mt][nt][2]);
            store_elem(C, bias, masks, mode, N, row0 + 8, col0 + 1, acc[mt][nt][3]);
        }
    }
}

// ------------------------- fused attention (scores+softmax+PV) --------------
#define ATTN_SMEM_FLOATS (128*68 + 64*68 + 64*68 + 256 + 256)
__global__ void __launch_bounds__(256) attn_kernel(
    const float* __restrict__ Q, const float* __restrict__ K,
    const float* __restrict__ VT, float* __restrict__ CC,
    const int* __restrict__ lengths)
{
    extern __shared__ float sm[];
    float* Ps   = sm;
    float* Ks   = sm + 128 * 68;
    float* Vs   = Ks + 64 * 68;
    float* smax = Vs + 64 * 68;
    float* ssum = smax + 256;

    const int qt = blockIdx.x, z = blockIdx.y;
    const int b = z >> 3, h = z & 7;
    const int q0 = qt * 128;
    const int len = __ldg(lengths + b);
    const int tid = threadIdx.x;
    const int warp = tid >> 5, lane = tid & 31;
    const int wm = warp >> 1, wn = warp & 1;
    const int g = lane >> 2, tg = lane & 3;

    const float* Qb = Q + ((size_t)z * NS + q0) * NDK;
#pragma unroll
    for (int i = 0; i < 8; i++) {
        const int idx = tid * 32 + i * 4;
        const int r = idx >> 6, c = idx & 63;
        float4 v = *(const float4*)(Qb + r * 64 + c);
        float* d = &Ps[r * 68 + c];
        d[0] = tf32r(v.x); d[1] = tf32r(v.y); d[2] = tf32r(v.z); d[3] = tf32r(v.w);
    }
    __syncthreads();

    unsigned qf[2][8][4];
#pragma unroll
    for (int mt = 0; mt < 2; mt++)
#pragma unroll
        for (int kb = 0; kb < 8; kb++) {
            const int rm = wm * 32 + mt * 16 + g;
            const int kk = kb * 8 + tg;
            qf[mt][kb][0] = __float_as_uint(Ps[rm * 68 + kk]);
            qf[mt][kb][1] = __float_as_uint(Ps[(rm + 8) * 68 + kk]);
            qf[mt][kb][2] = __float_as_uint(Ps[rm * 68 + kk + 4]);
            qf[mt][kb][3] = __float_as_uint(Ps[(rm + 8) * 68 + kk + 4]);
        }

    float oacc[2][4][4];
#pragma unroll
    for (int mt = 0; mt < 2; mt++)
#pragma unroll
        for (int nt = 0; nt < 4; nt++)
#pragma unroll
            for (int c = 0; c < 4; c++) oacc[mt][nt][c] = 0.f;
    float mrow[2][2] = {{-1e30f, -1e30f}, {-1e30f, -1e30f}};
    float srow[2][2] = {{0.f, 0.f}, {0.f, 0.f}};

    const int nch = (len + 63) >> 6;
    for (int kc = 0; kc < nch; kc++) {
        __syncthreads();
        const float* Kb = K + ((size_t)z * NS + kc * 64) * NDK;
#pragma unroll
        for (int i = 0; i < 4; i++) {
            const int idx = tid * 16 + i * 4;
            const int r = idx >> 6, c = idx & 63;
            float4 kv = *(const float4*)(Kb + r * 64 + c);
            float* dk = &Ks[r * 68 + c];
            dk[0] = tf32r(kv.x); dk[1] = tf32r(kv.y); dk[2] = tf32r(kv.z); dk[3] = tf32r(kv.w);
            float4 vv = *(const float4*)(VT + ((size_t)z * 64 + r) * NS + kc * 64 + c);
            float* dv = &Vs[r * 68 + c];
            dv[0] = tf32r(vv.x); dv[1] = tf32r(vv.y); dv[2] = tf32r(vv.z); dv[3] = tf32r(vv.w);
        }
        __syncthreads();
        float sacc[2][4][4];
#pragma unroll
        for (int mt = 0; mt < 2; mt++)
#pragma unroll
            for (int nt = 0; nt < 4; nt++)
#pragma unroll
                for (int c = 0; c < 4; c++) sacc[mt][nt][c] = 0.f;
#pragma unroll
        for (int kb = 0; kb < 8; kb++) {
            const int kk = kb * 8 + tg;
            unsigned bf[4][2];
#pragma unroll
            for (int nt = 0; nt < 4; nt++) {
                const int rn = wn * 32 + nt * 8 + g;
                bf[nt][0] = __float_as_uint(Ks[rn * 68 + kk]);
                bf[nt][1] = __float_as_uint(Ks[rn * 68 + kk + 4]);
            }
#pragma unroll
            for (int mt = 0; mt < 2; mt++)
#pragma unroll
                for (int nt = 0; nt < 4; nt++)
                    mma_tf32(sacc[mt][nt], qf[mt][kb], bf[nt]);
        }
#pragma unroll
        for (int mt = 0; mt < 2; mt++)
#pragma unroll
            for (int nt = 0; nt < 4; nt++) {
                const int col = kc * 64 + wn * 32 + nt * 8 + 2 * tg;
                const bool ok0 = col < len, ok1 = col + 1 < len;
                sacc[mt][nt][0] = ok0 ? sacc[mt][nt][0] * 0.125f : -1e30f;
                sacc[mt][nt][1] = ok1 ? sacc[mt][nt][1] * 0.125f : -1e30f;
                sacc[mt][nt][2] = ok0 ? sacc[mt][nt][2] * 0.125f : -1e30f;
                sacc[mt][nt][3] = ok1 ? sacc[mt][nt][3] * 0.125f : -1e30f;
            }
        float cmax[2][2] = {{-1e30f, -1e30f}, {-1e30f, -1e30f}};
#pragma unroll
        for (int mt = 0; mt < 2; mt++)
#pragma unroll
            for (int nt = 0; nt < 4; nt++) {
                cmax[mt][0] = fmaxf(cmax[mt][0], fmaxf(sacc[mt][nt][0], sacc[mt][nt][1]));
                cmax[mt][1] = fmaxf(cmax[mt][1], fmaxf(sacc[mt][nt][2], sacc[mt][nt][3]));
            }
#pragma unroll
        for (int off = 1; off < 4; off <<= 1)
#pragma unroll
            for (int mt = 0; mt < 2; mt++) {
                cmax[mt][0] = fmaxf(cmax[mt][0], __shfl_xor_sync(~0u, cmax[mt][0], off));
                cmax[mt][1] = fmaxf(cmax[mt][1], __shfl_xor_sync(~0u, cmax[mt][1], off));
            }
        if (tg == 0) {
#pragma unroll
            for (int mt = 0; mt < 2; mt++) {
                smax[wn * 128 + wm * 32 + mt * 16 + g]     = cmax[mt][0];
                smax[wn * 128 + wm * 32 + mt * 16 + 8 + g] = cmax[mt][1];
            }
        }
        __syncthreads();
        float alpha[2][2], csum[2][2] = {{0.f, 0.f}, {0.f, 0.f}};
#pragma unroll
        for (int mt = 0; mt < 2; mt++)
#pragma unroll
            for (int hh = 0; hh < 2; hh++) {
                const int row = wm * 32 + mt * 16 + hh * 8 + g;
                const float cm = fmaxf(smax[row], smax[128 + row]);
                const float mn = fmaxf(mrow[mt][hh], cm);
                alpha[mt][hh] = __expf(mrow[mt][hh] - mn);
                mrow[mt][hh] = mn;
            }
#pragma unroll
        for (int mt = 0; mt < 2; mt++)
#pragma unroll
            for (int nt = 0; nt < 4; nt++) {
                sacc[mt][nt][0] = __expf(sacc[mt][nt][0] - mrow[mt][0]);
                sacc[mt][nt][1] = __expf(sacc[mt][nt][1] - mrow[mt][0]);
                sacc[mt][nt][2] = __expf(sacc[mt][nt][2] - mrow[mt][1]);
                sacc[mt][nt][3] = __expf(sacc[mt][nt][3] - mrow[mt][1]);
                csum[mt][0] += sacc[mt][nt][0] + sacc[mt][nt][1];
                csum[mt][1] += sacc[mt][nt][2] + sacc[mt][nt][3];
            }
#pragma unroll
        for (int off = 1; off < 4; off <<= 1)
#pragma unroll
            for (int mt = 0; mt < 2; mt++) {
                csum[mt][0] += __shfl_xor_sync(~0u, csum[mt][0], off);
                csum[mt][1] += __shfl_xor_sync(~0u, csum[mt][1], off);
            }
        if (tg == 0) {
#pragma unroll
            for (int mt = 0; mt < 2; mt++) {
                ssum[wn * 128 + wm * 32 + mt * 16 + g]     = csum[mt][0];
                ssum[wn * 128 + wm * 32 + mt * 16 + 8 + g] = csum[mt][1];
            }
        }
#pragma unroll
        for (int mt = 0; mt < 2; mt++)
#pragma unroll
            for (int nt = 0; nt < 4; nt++) {
                oacc[mt][nt][0] *= alpha[mt][0];
                oacc[mt][nt][1] *= alpha[mt][0];
                oacc[mt][nt][2] *= alpha[mt][1];
                oacc[mt][nt][3] *= alpha[mt][1];
                const int r0 = wm * 32 + mt * 16 + g;
                const int col = wn * 32 + nt * 8 + 2 * tg;
                Ps[r0 * 68 + col]           = tf32r(sacc[mt][nt][0]);
                Ps[r0 * 68 + col + 1]       = tf32r(sacc[mt][nt][1]);
                Ps[(r0 + 8) * 68 + col]     = tf32r(sacc[mt][nt][2]);
                Ps[(r0 + 8) * 68 + col + 1] = tf32r(sacc[mt][nt][3]);
            }
        __syncthreads();
#pragma unroll
        for (int mt = 0; mt < 2; mt++)
#pragma unroll
            for (int hh = 0; hh < 2; hh++) {
                const int row = wm * 32 + mt * 16 + hh * 8 + g;
                srow[mt][hh] = srow[mt][hh] * alpha[mt][hh] + ssum[row] + ssum[128 + row];
            }
#pragma unroll
        for (int kb = 0; kb < 8; kb++) {
            const int kk = kb * 8 + tg;
            unsigned af[2][4], bf[4][2];
#pragma unroll
            for (int mt = 0; mt < 2; mt++) {
                const int rm = wm * 32 + mt * 16 + g;
                af[mt][0] = __float_as_uint(Ps[rm * 68 + kk]);
                af[mt][1] = __float_as_uint(Ps[(rm + 8) * 68 + kk]);
                af[mt][2] = __float_as_uint(Ps[rm * 68 + kk + 4]);
                af[mt][3] = __float_as_uint(Ps[(rm + 8) * 68 + kk + 4]);
            }
#pragma unroll
            for (int nt = 0; nt < 4; nt++) {
                const int rn = wn * 32 + nt * 8 + g;
                bf[nt][0] = __float_as_uint(Vs[rn * 68 + kk]);
                bf[nt][1] = __float_as_uint(Vs[rn * 68 + kk + 4]);
            }
#pragma unroll
            for (int mt = 0; mt < 2; mt++)
#pragma unroll
                for (int nt = 0; nt < 4; nt++)
                    mma_tf32(oacc[mt][nt], af[mt], bf[nt]);
        }
    }
#pragma unroll
    for (int mt = 0; mt < 2; mt++) {
        const float i0 = 1.f / srow[mt][0];
        const float i1 = 1.f / srow[mt][1];
        const int r0 = q0 + wm * 32 + mt * 16 + g;
        const bool ok0 = r0 < len, ok1 = (r0 + 8) < len;
#pragma unroll
        for (int nt = 0; nt < 4; nt++) {
            const int col = h * 64 + wn * 32 + nt * 8 + 2 * tg;
            float2 v0, v1;
            v0.x = ok0 ? oacc[mt][nt][0] * i0 : 0.f;
            v0.y = ok0 ? oacc[mt][nt][1] * i0 : 0.f;
            v1.x = ok1 ? oacc[mt][nt][2] * i1 : 0.f;
            v1.y = ok1 ? oacc[mt][nt][3] * i1 : 0.f;
            *(float2*)&CC[((size_t)b * NS + r0) * ND + col]     = v0;
            *(float2*)&CC[((size_t)b * NS + r0 + 8) * ND + col] = v1;
        }
    }
}

// ------------------------- flag reset -------------------------
__global__ void reset_kernel() {
    g_flag[blockIdx.x * 256 + threadIdx.x] = 0u;
}

// ------------------------- persistent GRU (round-7/13 proven version) -------
__global__ void __launch_bounds__(384, 1) gru_kernel(
    const float* __restrict__ whf, const float* __restrict__ whb,
    const float* __restrict__ bhf, const float* __restrict__ bhb,
    const int* __restrict__ masks, float* __restrict__ hid_out)
{
    __shared__ float sh_h[1024];
    __shared__ float sh_gate[384];

    const int bid = blockIdx.x;
    const int dir = bid >> 6;
    const int rem = bid & 63;
    const int bg  = rem >> 3;
    const int jc  = rem & 7;
    const int grp = dir * 8 + bg;
    const int tid = threadIdx.x;
    const int rg  = tid >> 3;
    const int ks  = tid & 7;
    const int row0 = rg * 2, row1 = rg * 2 + 1;
    const int G0 = (row0 >> 5) * 256 + jc * 32 + (row0 & 31);
    const int G1 = (row1 >> 5) * 256 + jc * 32 + (row1 & 31);

    const float* wh = dir ? whb : whf;
    const float* bh = dir ? bhb : bhf;
    const float bh0 = bh[G0], bh1 = bh[G1];

    unsigned long long wp0[16], wp1[16];
    {
        const float* w0s = wh + (long)G0 * NH2 + ks * 32;
        const float* w1s = wh + (long)G1 * NH2 + ks * 32;
#pragma unroll
        for (int i = 0; i < 16; i++) {
            wp0[i] = pack2(w0s[2 * i], w0s[2 * i + 1]);
            wp1[i] = pack2(w1s[2 * i], w1s[2 * i + 1]);
        }
    }

    const int ju = tid & 31, bu = tid >> 5;
    const int jglob = jc * 32 + ju;
    const int bglob = bg * 4 + bu;
    const float* xgp = g_xg + ((size_t)dir * NB + bglob) * NS * NG3;
    float* hxg = g_hx + grp * 2048;
    unsigned* myflag = &g_flag[(grp * 8 + jc) * 32];

    const int cb = tid >> 6, cc0 = tid & 63;
    const int csw = ((cc0 >> 3) << 3) | ((cc0 & 7) ^ (cc0 >> 3));
    float* shdst = &sh_h[cb * 256 + csw * 4];

    for (int i = tid; i < 1024; i += 384) sh_h[i] = 0.f;
    float hreg = 0.f;
    __syncthreads();

    for (int t = 0; t < NS; t++) {
        const int s = dir ? (NS - 1 - t) : t;
        float xr = 0.f, xz = 0.f, xn = 0.f;
        int mk = 0;
        if (tid < 128) {
            const float* xrow = xgp + (size_t)s * NG3;
            xr = __ldg(xrow + jglob);
            xz = __ldg(xrow + NH2 + jglob);
            xn = __ldg(xrow + 2 * NH2 + jglob);
            mk = __ldg(masks + bglob * NS + s);
        }
        if (t > 0) {
            if (tid < 8) {
                const unsigned* fp = &g_flag[(grp * 8 + tid) * 32];
                unsigned v;
                do {
                    asm volatile("ld.global.acquire.gpu.u32 %0, [%1];"
                                 : "=r"(v) : "l"(fp) : "memory");
                } while (v < (unsigned)t);
            }
            __syncthreads();
            if (tid < 256) {
                const float4* src = (const float4*)(hxg + ((t - 1) & 1) * 1024);
                float4 hv4;
                asm volatile("ld.global.cg.v4.f32 {%0,%1,%2,%3}, [%4];"
                             : "=f"(hv4.x), "=f"(hv4.y), "=f"(hv4.z), "=f"(hv4.w)
                             : "l"(src + tid) : "memory");
                *(float4*)shdst = hv4;
            }
            __syncthreads();
        }
        unsigned long long a0[4] = {0ull, 0ull, 0ull, 0ull};
        unsigned long long a1[4] = {0ull, 0ull, 0ull, 0ull};
#pragma unroll
        for (int i = 0; i < 8; i++) {
            const int coff = (((ks << 3) | (i ^ ks)) << 2);
#pragma unroll
            for (int b = 0; b < 4; b++) {
                ulonglong2 hv = *(const ulonglong2*)(sh_h + b * 256 + coff);
                a0[b] = fma2(wp0[2 * i],     hv.x, a0[b]);
                a0[b] = fma2(wp0[2 * i + 1], hv.y, a0[b]);
                a1[b] = fma2(wp1[2 * i],     hv.x, a1[b]);
                a1[b] = fma2(wp1[2 * i + 1], hv.y, a1[b]);
            }
        }
        float v0[4], v1[4];
#pragma unroll
        for (int b = 0; b < 4; b++) {
            float lo, hi;
            unpack2(a0[b], lo, hi); v0[b] = lo + hi;
            unpack2(a1[b], lo, hi); v1[b] = lo + hi;
        }
#pragma unroll
        for (int off = 1; off < 8; off <<= 1) {
#pragma unroll
            for (int b = 0; b < 4; b++) {
                v0[b] += __shfl_xor_sync(~0u, v0[b], off);
                v1[b] += __shfl_xor_sync(~0u, v1[b], off);
            }
        }
        if (ks == 0) {
            float4 f0 = make_float4(v0[0] + bh0, v0[1] + bh0, v0[2] + bh0, v0[3] + bh0);
            float4 f1 = make_float4(v1[0] + bh1, v1[1] + bh1, v1[2] + bh1, v1[3] + bh1);
            *(float4*)&sh_gate[rg * 8]     = f0;
            *(float4*)&sh_gate[rg * 8 + 4] = f1;
        }
        __syncthreads();
        if (tid < 128) {
            const float hgr = sh_gate[ju * 4 + bu];
            const float hgz = sh_gate[(32 + ju) * 4 + bu];
            const float hgn = sh_gate[(64 + ju) * 4 + bu];
            const float rr = 1.f / (1.f + __expf(-(xr + hgr)));
            const float zz = 1.f / (1.f + __expf(-(xz + hgz)));
            const float na = xn + rr * hgn;
            const float nn = 2.f / (1.f + __expf(-2.f * na)) - 1.f;
            const float hnew = (1.f - zz) * nn + zz * hreg;
            hreg = mk ? hnew : hreg;
            g_gru[((size_t)bglob * NS + s) * ND + dir * NH2 + jglob] = mk ? hreg : 0.f;
            if (t == NS - 1) {
                hid_out[bglob * ND + dir * NH2 + jglob] = hreg;
            } else {
                __stcg(hxg + (t & 1) * 1024 + bu * 256 + jglob, hreg);
            }
        }
        if (t < NS - 1) {
            __syncthreads();
            if (tid == 0) {
                __threadfence();
                unsigned nv = (unsigned)(t + 1);
                asm volatile("st.global.cg.u32 [%0], %1;"
                             :: "l"(myflag), "r"(nv) : "memory");
            }
        }
    }
}

// ------------------------- layernorm (optionally fused residual) ------------
__global__ void __launch_bounds__(128) ln_kernel(
    const float* __restrict__ x, const float* __restrict__ y,
    const float* __restrict__ gam, const float* __restrict__ bet,
    float* __restrict__ out)
{
    __shared__ float red[8];
    const int row = blockIdx.x;
    const int tid = threadIdx.x;
    float4 v = *(const float4*)(x + (size_t)row * ND + tid * 4);
    if (y) {
        float4 w = *(const float4*)(y + (size_t)row * ND + tid * 4);
        v.x += w.x; v.y += w.y; v.z += w.z; v.w += w.w;
    }
    float s1 = v.x + v.y + v.z + v.w;
    float s2 = v.x * v.x + v.y * v.y + v.z * v.z + v.w * v.w;
#pragma unroll
    for (int o = 16; o; o >>= 1) {
        s1 += __shfl_xor_sync(~0u, s1, o);
        s2 += __shfl_xor_sync(~0u, s2, o);
    }
    const int wid = tid >> 5;
    if ((tid & 31) == 0) { red[wid] = s1; red[wid + 4] = s2; }
    __syncthreads();
    s1 = red[0] + red[1] + red[2] + red[3];
    s2 = red[4] + red[5] + red[6] + red[7];
    const float mu = s1 * (1.f / ND);
    const float var = s2 * (1.f / ND) - mu * mu;
    const float rs = rsqrtf(var + 1e-5f);
    const float4 gv = *(const float4*)(gam + tid * 4);
    const float4 bv = *(const float4*)(bet + tid * 4);
    float4 o4;
    o4.x = (v.x - mu) * rs * gv.x + bv.x;
    o4.y = (v.y - mu) * rs * gv.y + bv.y;
    o4.z = (v.z - mu) * rs * gv.z + bv.z;
    o4.w = (v.w - mu) * rs * gv.w + bv.w;
    *(float4*)(out + (size_t)row * ND + tid * 4) = o4;
}

// ------------------------- launch -------------------------
extern "C" void kernel_launch(void* const* d_in, const int* in_sizes, int n_in,
                              void* d_out, int out_size)
{
    const float* splits = (const float*)d_in[0];
    const float* w_ih_f = (const float*)d_in[1];
    const float* w_hh_f = (const float*)d_in[2];
    const float* b_ih_f = (const float*)d_in[3];
    const float* b_hh_f = (const float*)d_in[4];
    const float* w_ih_b = (const float*)d_in[5];
    const float* w_hh_b = (const float*)d_in[6];
    const float* b_ih_b = (const float*)d_in[7];
    const float* b_hh_b = (const float*)d_in[8];
    const float* ln1_g  = (const float*)d_in[9];
    const float* ln1_b  = (const float*)d_in[10];
    const float* wq = (const float*)d_in[11];
    const float* bq = (const float*)d_in[12];
    const float* wk = (const float*)d_in[13];
    const float* bk = (const float*)d_in[14];
    const float* wv = (const float*)d_in[15];
    const float* bv = (const float*)d_in[16];
    const float* wo = (const float*)d_in[17];
    const float* bo = (const float*)d_in[18];
    const float* ln2_g = (const float*)d_in[19];
    const float* ln2_b = (const float*)d_in[20];
    const int* lengths = (const int*)d_in[21];
    const int* masks   = (const int*)d_in[22];
    float* out = (float*)d_out;

    float *xg, *gru, *ln1, *q, *k, *vt, *cc, *oo;
    cudaGetSymbolAddress((void**)&xg,  g_xg);
    cudaGetSymbolAddress((void**)&gru, g_gru);
    cudaGetSymbolAddress((void**)&ln1, g_ln1);
    cudaGetSymbolAddress((void**)&q,   g_q);
    cudaGetSymbolAddress((void**)&k,   g_k);
    cudaGetSymbolAddress((void**)&vt,  g_vt);
    cudaGetSymbolAddress((void**)&cc,  g_cc);
    cudaGetSymbolAddress((void**)&oo,  g_o);

    const int M = NB * NS;  // 16384
    const int ATTN_SMEM = ATTN_SMEM_FLOATS * 4;
    cudaFuncSetAttribute(attn_kernel, cudaFuncAttributeMaxDynamicSharedMemorySize, ATTN_SMEM);
    cudaFuncSetAttribute(gemm3, cudaFuncAttributeMaxDynamicSharedMemorySize, G3_SMEM);

    // GRU input projections — one launch, z = dir; prefix-mask tile skip
    gemm3<<<dim3(6, 128, 2), 256, G3_SMEM>>>(
        splits, w_ih_f, w_ih_b, nullptr, b_ih_f, b_ih_b, nullptr,
        xg, xg + (size_t)M * NG3, nullptr, 0, 0, 0,
        M, NG3, ND, masks);
    // GRU recurrence (persistent, per-rank flag sync through L2)
    reset_kernel<<<16, 256>>>();
    gru_kernel<<<128, 384>>>(w_hh_f, w_hh_b, b_hh_f, b_hh_b, masks,
                             out + (size_t)NB * NS * ND);
    // LN1
    ln_kernel<<<M, 128>>>(gru, nullptr, ln1_g, ln1_b, ln1);
    // Q/K/V projections — one launch, z = {q, k, v}; prefix-mask tile skip
    gemm3<<<dim3(4, 128, 3), 256, G3_SMEM>>>(
        ln1, wq, wk, wv, bq, bk, bv,
        q, k, vt, 1, 1, 2,
        M, ND, ND, masks);
    // fused attention: scores + masked online softmax + PV -> concat
    attn_kernel<<<dim3(4, 256), 256, ATTN_SMEM>>>(q, k, vt, cc, lengths);
    // out projection + row mask (skip writes zero tiles)
    gemm3<<<dim3(4, 128, 1), 256, G3_SMEM>>>(
        cc, wo, nullptr, nullptr, bo, nullptr, nullptr,
        oo, nullptr, nullptr, 5, 5, 5,
        M, ND, ND, masks);
    // residual + LN2 -> final outputs
    ln_kernel<<<M, 128>>>(ln1, oo, ln2_g, ln2_b, out);
}

// round 17
// speedup vs baseline: 1.1460x; 1.0504x over previous
#include <cuda_runtime.h>
#include <cstdint>
#include <cstddef>

#define NB   32
#define NS   512
#define ND   512
#define NH2  256
#define NG3  768
#define NDK  64

// ------------------------- scratch (device globals) -------------------------
__device__ float g_xg[(size_t)2 * NB * NS * NG3];   // gate preactivations, per dir
__device__ float g_gru[(size_t)NB * NS * ND];       // concat GRU outputs
__device__ float g_ln1[(size_t)NB * NS * ND];       // ln1("outputs")
__device__ float g_q [(size_t)NB * 8 * NS * NDK];   // (b,h,s,d)
__device__ float g_k [(size_t)NB * 8 * NS * NDK];   // (b,h,s,d)
__device__ float g_vt[(size_t)NB * 8 * NDK * NS];   // (b,h,d,s)
__device__ float g_cc[(size_t)NB * NS * ND];        // attn concat
__device__ float g_o [(size_t)NB * NS * ND];        // out projection
__device__ float g_hx[16 * 2048];                   // h exchange (16 groups x 2 bufs x 1024)
__device__ unsigned g_flag[16 * 8 * 32];            // per (group,rank) step flag, 1 per 128B line

// ------------------------- helpers -------------------------
__device__ __forceinline__ unsigned long long fma2(unsigned long long a,
                                                   unsigned long long b,
                                                   unsigned long long c) {
    unsigned long long d;
    asm("fma.rn.f32x2 %0, %1, %2, %3;" : "=l"(d) : "l"(a), "l"(b), "l"(c));
    return d;
}
__device__ __forceinline__ unsigned long long pack2(float x, float y) {
    unsigned long long d;
    asm("mov.b64 %0, {%1, %2};" : "=l"(d) : "f"(x), "f"(y));
    return d;
}
__device__ __forceinline__ void unpack2(unsigned long long v, float& x, float& y) {
    asm("mov.b64 {%0, %1}, %2;" : "=f"(x), "=f"(y) : "l"(v));
}
__device__ __forceinline__ float tf32r(float f) {
    unsigned u;
    asm("cvt.rna.tf32.f32 %0, %1;" : "=r"(u) : "f"(f));
    return __uint_as_float(u);
}
__device__ __forceinline__ void mma_tf32(float* acc, const unsigned* a, const unsigned* b) {
    asm volatile(
        "mma.sync.aligned.m16n8k8.row.col.f32.tf32.tf32.f32 "
        "{%0,%1,%2,%3}, {%4,%5,%6,%7}, {%8,%9}, {%0,%1,%2,%3};"
        : "+f"(acc[0]), "+f"(acc[1]), "+f"(acc[2]), "+f"(acc[3])
        : "r"(a[0]), "r"(a[1]), "r"(a[2]), "r"(a[3]),
          "r"(b[0]), "r"(b[1]));
}

// ------------------------- epilogue store -------------------------
// 0: +bias   1: +bias, scatter (b,h,s,d)   2: +bias, scatter (b,h,d,s)
// 5: +bias, *rowmask(masks)
__device__ __forceinline__ void store_elem(float* C, const float* bias,
                                           const int* masks, int mode,
                                           int N, int mrow, int nc, float v) {
    if (mode == 0) {
        C[(size_t)mrow * N + nc] = v + bias[nc];
    } else if (mode == 1) {
        int b = mrow >> 9, s = mrow & 511, h = nc >> 6, d = nc & 63;
        C[(((size_t)(b * 8 + h) * NS + s)) * NDK + d] = v + bias[nc];
    } else if (mode == 2) {
        int b = mrow >> 9, s = mrow & 511, h = nc >> 6, d = nc & 63;
        C[((size_t)(b * 8 + h) * NDK + d) * NS + s] = v + bias[nc];
    } else {
        C[(size_t)mrow * N + nc] = masks[mrow] ? (v + bias[nc]) : 0.f;
    }
}

// ------------------------- tf32 TN GEMM, double-buffered, up to 3 ops/z -----
// C = epi(A[M,K] @ W[N,K]^T). Requires M%128==0, N%128==0, K%32==0.
// Prefix-mask tile skip: if first row of the 128-row tile is masked, the
// tile is immaterial downstream (mode 5: writes exact zeros).
#define G3_SMEM (2 * 2 * 128 * 36 * 4)
__global__ void __launch_bounds__(256) gemm3(
    const float* __restrict__ A,
    const float* __restrict__ W0, const float* __restrict__ W1, const float* __restrict__ W2,
    const float* __restrict__ b0, const float* __restrict__ b1, const float* __restrict__ b2,
    float* __restrict__ C0, float* __restrict__ C1, float* __restrict__ C2,
    int mode0, int mode1, int mode2,
    int M, int N, int K, const int* __restrict__ masks)
{
    extern __shared__ float smg[];
    float* Asm = smg;                 // [2][128][36]
    float* Wsm = smg + 2 * 128 * 36;  // [2][128][36]

    const int z = blockIdx.z;
    const float* W    = (z == 0) ? W0 : (z == 1) ? W1 : W2;
    const float* bias = (z == 0) ? b0 : (z == 1) ? b1 : b2;
    float* C          = (z == 0) ? C0 : (z == 1) ? C1 : C2;
    const int mode    = (z == 0) ? mode0 : (z == 1) ? mode1 : mode2;

    const int m0 = blockIdx.y * 128, n0 = blockIdx.x * 128;
    const int tid  = threadIdx.x;

    // ---- prefix-mask tile skip ----
    if (masks && __ldg(masks + m0) == 0) {
        if (mode == 5) {
            for (int i = tid; i < 128 * 32; i += 256) {
                const int r = i >> 5, c4 = i & 31;
                *(float4*)&C[(size_t)(m0 + r) * N + n0 + c4 * 4] =
                    make_float4(0.f, 0.f, 0.f, 0.f);
            }
        }
        return;
    }

    const int warp = tid >> 5, lane = tid & 31;
    const int wm = warp >> 2, wn = warp & 3;
    const int g  = lane >> 2, tg = lane & 3;

    const int lrow = tid >> 1, lkq = tid & 1;
    const float* Ap = A + (size_t)(m0 + lrow) * K + lkq * 16;
    const float* Wp = W + (size_t)(n0 + lrow) * K + lkq * 16;
    const int dsto = lrow * 36 + lkq * 16;

    float acc[4][4][4];
#pragma unroll
    for (int mt = 0; mt < 4; mt++)
#pragma unroll
        for (int nt = 0; nt < 4; nt++)
#pragma unroll
            for (int c = 0; c < 4; c++) acc[mt][nt][c] = 0.f;

    float4 ar[4], wr[4];
#pragma unroll
    for (int i = 0; i < 4; i++) {
        ar[i] = *(const float4*)(Ap + i * 4);
        wr[i] = *(const float4*)(Wp + i * 4);
    }
#pragma unroll
    for (int i = 0; i < 4; i++) {
        float4 c;
        c.x = tf32r(ar[i].x); c.y = tf32r(ar[i].y);
        c.z = tf32r(ar[i].z); c.w = tf32r(ar[i].w);
        *(float4*)(Asm + dsto + i * 4) = c;
        c.x = tf32r(wr[i].x); c.y = tf32r(wr[i].y);
        c.z = tf32r(wr[i].z); c.w = tf32r(wr[i].w);
        *(float4*)(Wsm + dsto + i * 4) = c;
    }
    __syncthreads();

    const int niter = K >> 5;
    int p = 0;
    for (int it = 0; it < niter; ++it) {
        if (it + 1 < niter) {
            const int ko = (it + 1) << 5;
#pragma unroll
            for (int i = 0; i < 4; i++) {
                ar[i] = *(const float4*)(Ap + ko + i * 4);
                wr[i] = *(const float4*)(Wp + ko + i * 4);
            }
        }
        const float* ab = Asm + p * (128 * 36);
        const float* wb = Wsm + p * (128 * 36);
#pragma unroll
        for (int kb = 0; kb < 4; kb++) {
            const int kk = kb * 8 + tg;
            unsigned a[4][4], b[4][2];
#pragma unroll
            for (int mt = 0; mt < 4; mt++) {
                const int rm = wm * 64 + mt * 16 + g;
                a[mt][0] = __float_as_uint(ab[rm * 36 + kk]);
                a[mt][1] = __float_as_uint(ab[(rm + 8) * 36 + kk]);
                a[mt][2] = __float_as_uint(ab[rm * 36 + kk + 4]);
                a[mt][3] = __float_as_uint(ab[(rm + 8) * 36 + kk + 4]);
            }
#pragma unroll
            for (int nt = 0; nt < 4; nt++) {
                const int rn = wn * 32 + nt * 8 + g;
                b[nt][0] = __float_as_uint(wb[rn * 36 + kk]);
                b[nt][1] = __float_as_uint(wb[rn * 36 + kk + 4]);
            }
#pragma unroll
            for (int mt = 0; mt < 4; mt++)
#pragma unroll
                for (int nt = 0; nt < 4; nt++)
                    mma_tf32(acc[mt][nt], a[mt], b[nt]);
        }
        if (it + 1 < niter) {
            float* ad = Asm + (p ^ 1) * (128 * 36) + dsto;
            float* wd = Wsm + (p ^ 1) * (128 * 36) + dsto;
#pragma unroll
            for (int i = 0; i < 4; i++) {
                float4 c;
                c.x = tf32r(ar[i].x); c.y = tf32r(ar[i].y);
                c.z = tf32r(ar[i].z); c.w = tf32r(ar[i].w);
                *(float4*)(ad + i * 4) = c;
                c.x = tf32r(wr[i].x); c.y = tf32r(wr[i].y);
                c.z = tf32r(wr[i].z); c.w = tf32r(wr[i].w);
                *(float4*)(wd + i * 4) = c;
            }
        }
        __syncthreads();
        p ^= 1;
    }

#pragma unroll
    for (int mt = 0; mt < 4; mt++) {
#pragma unroll
        for (int nt = 0; nt < 4; nt++) {
            const int row0 = m0 + wm * 64 + mt * 16 + g;
            const int col0 = n0 + wn * 32 + nt * 8 + 2 * tg;
            store_elem(C, bias, masks, mode, N, row0,     col0,     acc[mt][nt][0]);
            store_elem(C, bias, masks, mode, N, row0,     col0 + 1, acc[mt][nt][1]);
            store_elem(C, bias, masks, mode, N, row0 + 8, col0,     acc[mt][nt][2]);
            store_elem(C, bias, masks, mode, N, row0 + 8, col0 + 1, acc[mt][nt][3]);
        }
    }
}

// ------------------------- fused attention (scores+softmax+PV) --------------
#define ATTN_SMEM_FLOATS (128*68 + 64*68 + 64*68 + 256 + 256)
__global__ void __launch_bounds__(256) attn_kernel(
    const float* __restrict__ Q, const float* __restrict__ K,
    const float* __restrict__ VT, float* __restrict__ CC,
    const int* __restrict__ lengths)
{
    extern __shared__ float sm[];
    float* Ps   = sm;
    float* Ks   = sm + 128 * 68;
    float* Vs   = Ks + 64 * 68;
    float* smax = Vs + 64 * 68;
    float* ssum = smax + 256;

    const int qt = blockIdx.x, z = blockIdx.y;
    const int b = z >> 3, h = z & 7;
    const int q0 = qt * 128;
    const int len = __ldg(lengths + b);
    // fully masked q-tile: its CC rows are never read (out-proj tile is
    // mask-skipped and writes zeros itself) — nothing to do.
    if (q0 >= len) return;
    const int tid = threadIdx.x;
    const int warp = tid >> 5, lane = tid & 31;
    const int wm = warp >> 1, wn = warp & 1;
    const int g = lane >> 2, tg = lane & 3;

    const float* Qb = Q + ((size_t)z * NS + q0) * NDK;
#pragma unroll
    for (int i = 0; i < 8; i++) {
        const int idx = tid * 32 + i * 4;
        const int r = idx >> 6, c = idx & 63;
        float4 v = *(const float4*)(Qb + r * 64 + c);
        float* d = &Ps[r * 68 + c];
        d[0] = tf32r(v.x); d[1] = tf32r(v.y); d[2] = tf32r(v.z); d[3] = tf32r(v.w);
    }
    __syncthreads();

    unsigned qf[2][8][4];
#pragma unroll
    for (int mt = 0; mt < 2; mt++)
#pragma unroll
        for (int kb = 0; kb < 8; kb++) {
            const int rm = wm * 32 + mt * 16 + g;
            const int kk = kb * 8 + tg;
            qf[mt][kb][0] = __float_as_uint(Ps[rm * 68 + kk]);
            qf[mt][kb][1] = __float_as_uint(Ps[(rm + 8) * 68 + kk]);
            qf[mt][kb][2] = __float_as_uint(Ps[rm * 68 + kk + 4]);
            qf[mt][kb][3] = __float_as_uint(Ps[(rm + 8) * 68 + kk + 4]);
        }

    float oacc[2][4][4];
#pragma unroll
    for (int mt = 0; mt < 2; mt++)
#pragma unroll
        for (int nt = 0; nt < 4; nt++)
#pragma unroll
            for (int c = 0; c < 4; c++) oacc[mt][nt][c] = 0.f;
    float mrow[2][2] = {{-1e30f, -1e30f}, {-1e30f, -1e30f}};
    float srow[2][2] = {{0.f, 0.f}, {0.f, 0.f}};

    const int nch = (len + 63) >> 6;
    for (int kc = 0; kc < nch; kc++) {
        __syncthreads();
        const float* Kb = K + ((size_t)z * NS + kc * 64) * NDK;
#pragma unroll
        for (int i = 0; i < 4; i++) {
            const int idx = tid * 16 + i * 4;
            const int r = idx >> 6, c = idx & 63;
            float4 kv = *(const float4*)(Kb + r * 64 + c);
            float* dk = &Ks[r * 68 + c];
            dk[0] = tf32r(kv.x); dk[1] = tf32r(kv.y); dk[2] = tf32r(kv.z); dk[3] = tf32r(kv.w);
            float4 vv = *(const float4*)(VT + ((size_t)z * 64 + r) * NS + kc * 64 + c);
            float* dv = &Vs[r * 68 + c];
            dv[0] = tf32r(vv.x); dv[1] = tf32r(vv.y); dv[2] = tf32r(vv.z); dv[3] = tf32r(vv.w);
        }
        __syncthreads();
        float sacc[2][4][4];
#pragma unroll
        for (int mt = 0; mt < 2; mt++)
#pragma unroll
            for (int nt = 0; nt < 4; nt++)
#pragma unroll
                for (int c = 0; c < 4; c++) sacc[mt][nt][c] = 0.f;
#pragma unroll
        for (int kb = 0; kb < 8; kb++) {
            const int kk = kb * 8 + tg;
            unsigned bf[4][2];
#pragma unroll
            for (int nt = 0; nt < 4; nt++) {
                const int rn = wn * 32 + nt * 8 + g;
                bf[nt][0] = __float_as_uint(Ks[rn * 68 + kk]);
                bf[nt][1] = __float_as_uint(Ks[rn * 68 + kk + 4]);
            }
#pragma unroll
            for (int mt = 0; mt < 2; mt++)
#pragma unroll
                for (int nt = 0; nt < 4; nt++)
                    mma_tf32(sacc[mt][nt], qf[mt][kb], bf[nt]);
        }
#pragma unroll
        for (int mt = 0; mt < 2; mt++)
#pragma unroll
            for (int nt = 0; nt < 4; nt++) {
                const int col = kc * 64 + wn * 32 + nt * 8 + 2 * tg;
                const bool ok0 = col < len, ok1 = col + 1 < len;
                sacc[mt][nt][0] = ok0 ? sacc[mt][nt][0] * 0.125f : -1e30f;
                sacc[mt][nt][1] = ok1 ? sacc[mt][nt][1] * 0.125f : -1e30f;
                sacc[mt][nt][2] = ok0 ? sacc[mt][nt][2] * 0.125f : -1e30f;
                sacc[mt][nt][3] = ok1 ? sacc[mt][nt][3] * 0.125f : -1e30f;
            }
        float cmax[2][2] = {{-1e30f, -1e30f}, {-1e30f, -1e30f}};
#pragma unroll
        for (int mt = 0; mt < 2; mt++)
#pragma unroll
            for (int nt = 0; nt < 4; nt++) {
                cmax[mt][0] = fmaxf(cmax[mt][0], fmaxf(sacc[mt][nt][0], sacc[mt][nt][1]));
                cmax[mt][1] = fmaxf(cmax[mt][1], fmaxf(sacc[mt][nt][2], sacc[mt][nt][3]));
            }
#pragma unroll
        for (int off = 1; off < 4; off <<= 1)
#pragma unroll
            for (int mt = 0; mt < 2; mt++) {
                cmax[mt][0] = fmaxf(cmax[mt][0], __shfl_xor_sync(~0u, cmax[mt][0], off));
                cmax[mt][1] = fmaxf(cmax[mt][1], __shfl_xor_sync(~0u, cmax[mt][1], off));
            }
        if (tg == 0) {
#pragma unroll
            for (int mt = 0; mt < 2; mt++) {
                smax[wn * 128 + wm * 32 + mt * 16 + g]     = cmax[mt][0];
                smax[wn * 128 + wm * 32 + mt * 16 + 8 + g] = cmax[mt][1];
            }
        }
        __syncthreads();
        float alpha[2][2], csum[2][2] = {{0.f, 0.f}, {0.f, 0.f}};
#pragma unroll
        for (int mt = 0; mt < 2; mt++)
#pragma unroll
            for (int hh = 0; hh < 2; hh++) {
                const int row = wm * 32 + mt * 16 + hh * 8 + g;
                const float cm = fmaxf(smax[row], smax[128 + row]);
                const float mn = fmaxf(mrow[mt][hh], cm);
                alpha[mt][hh] = __expf(mrow[mt][hh] - mn);
                mrow[mt][hh] = mn;
            }
#pragma unroll
        for (int mt = 0; mt < 2; mt++)
#pragma unroll
            for (int nt = 0; nt < 4; nt++) {
                sacc[mt][nt][0] = __expf(sacc[mt][nt][0] - mrow[mt][0]);
                sacc[mt][nt][1] = __expf(sacc[mt][nt][1] - mrow[mt][0]);
                sacc[mt][nt][2] = __expf(sacc[mt][nt][2] - mrow[mt][1]);
                sacc[mt][nt][3] = __expf(sacc[mt][nt][3] - mrow[mt][1]);
                csum[mt][0] += sacc[mt][nt][0] + sacc[mt][nt][1];
                csum[mt][1] += sacc[mt][nt][2] + sacc[mt][nt][3];
            }
#pragma unroll
        for (int off = 1; off < 4; off <<= 1)
#pragma unroll
            for (int mt = 0; mt < 2; mt++) {
                csum[mt][0] += __shfl_xor_sync(~0u, csum[mt][0], off);
                csum[mt][1] += __shfl_xor_sync(~0u, csum[mt][1], off);
            }
        if (tg == 0) {
#pragma unroll
            for (int mt = 0; mt < 2; mt++) {
                ssum[wn * 128 + wm * 32 + mt * 16 + g]     = csum[mt][0];
                ssum[wn * 128 + wm * 32 + mt * 16 + 8 + g] = csum[mt][1];
            }
        }
#pragma unroll
        for (int mt = 0; mt < 2; mt++)
#pragma unroll
            for (int nt = 0; nt < 4; nt++) {
                oacc[mt][nt][0] *= alpha[mt][0];
                oacc[mt][nt][1] *= alpha[mt][0];
                oacc[mt][nt][2] *= alpha[mt][1];
                oacc[mt][nt][3] *= alpha[mt][1];
                const int r0 = wm * 32 + mt * 16 + g;
                const int col = wn * 32 + nt * 8 + 2 * tg;
                Ps[r0 * 68 + col]           = tf32r(sacc[mt][nt][0]);
                Ps[r0 * 68 + col + 1]       = tf32r(sacc[mt][nt][1]);
                Ps[(r0 + 8) * 68 + col]     = tf32r(sacc[mt][nt][2]);
                Ps[(r0 + 8) * 68 + col + 1] = tf32r(sacc[mt][nt][3]);
            }
        __syncthreads();
#pragma unroll
        for (int mt = 0; mt < 2; mt++)
#pragma unroll
            for (int hh = 0; hh < 2; hh++) {
                const int row = wm * 32 + mt * 16 + hh * 8 + g;
                srow[mt][hh] = srow[mt][hh] * alpha[mt][hh] + ssum[row] + ssum[128 + row];
            }
#pragma unroll
        for (int kb = 0; kb < 8; kb++) {
            const int kk = kb * 8 + tg;
            unsigned af[2][4], bf[4][2];
#pragma unroll
            for (int mt = 0; mt < 2; mt++) {
                const int rm = wm * 32 + mt * 16 + g;
                af[mt][0] = __float_as_uint(Ps[rm * 68 + kk]);
                af[mt][1] = __float_as_uint(Ps[(rm + 8) * 68 + kk]);
                af[mt][2] = __float_as_uint(Ps[rm * 68 + kk + 4]);
                af[mt][3] = __float_as_uint(Ps[(rm + 8) * 68 + kk + 4]);
            }
#pragma unroll
            for (int nt = 0; nt < 4; nt++) {
                const int rn = wn * 32 + nt * 8 + g;
                bf[nt][0] = __float_as_uint(Vs[rn * 68 + kk]);
                bf[nt][1] = __float_as_uint(Vs[rn * 68 + kk + 4]);
            }
#pragma unroll
            for (int mt = 0; mt < 2; mt++)
#pragma unroll
                for (int nt = 0; nt < 4; nt++)
                    mma_tf32(oacc[mt][nt], af[mt], bf[nt]);
        }
    }
#pragma unroll
    for (int mt = 0; mt < 2; mt++) {
        const float i0 = 1.f / srow[mt][0];
        const float i1 = 1.f / srow[mt][1];
        const int r0 = q0 + wm * 32 + mt * 16 + g;
        const bool ok0 = r0 < len, ok1 = (r0 + 8) < len;
#pragma unroll
        for (int nt = 0; nt < 4; nt++) {
            const int col = h * 64 + wn * 32 + nt * 8 + 2 * tg;
            float2 v0, v1;
            v0.x = ok0 ? oacc[mt][nt][0] * i0 : 0.f;
            v0.y = ok0 ? oacc[mt][nt][1] * i0 : 0.f;
            v1.x = ok1 ? oacc[mt][nt][2] * i1 : 0.f;
            v1.y = ok1 ? oacc[mt][nt][3] * i1 : 0.f;
            *(float2*)&CC[((size_t)b * NS + r0) * ND + col]     = v0;
            *(float2*)&CC[((size_t)b * NS + r0 + 8) * ND + col] = v1;
        }
    }
}

// ------------------------- flag reset -------------------------
__global__ void reset_kernel() {
    g_flag[blockIdx.x * 256 + threadIdx.x] = 0u;
}

// ------------------------- persistent GRU (length-aware step skip) ----------
// Group maxlen = max over its 4 batches. All steps s >= maxlen are no-ops for
// both directions (fwd: h frozen + zero output; bwd: h stays 0 + zero output).
// Zero-fill those outputs, then run only maxlen steps (fwd s=tt; bwd
// s=maxlen-1-tt). Flags indexed by tt — same maxlen across the group's 8
// blocks, mailbox invariants unchanged.
__global__ void __launch_bounds__(384, 1) gru_kernel(
    const float* __restrict__ whf, const float* __restrict__ whb,
    const float* __restrict__ bhf, const float* __restrict__ bhb,
    const int* __restrict__ masks, const int* __restrict__ lengths,
    float* __restrict__ hid_out)
{
    __shared__ float sh_h[1024];
    __shared__ float sh_gate[384];

    const int bid = blockIdx.x;
    const int dir = bid >> 6;
    const int rem = bid & 63;
    const int bg  = rem >> 3;
    const int jc  = rem & 7;
    const int grp = dir * 8 + bg;
    const int tid = threadIdx.x;
    const int rg  = tid >> 3;
    const int ks  = tid & 7;
    const int row0 = rg * 2, row1 = rg * 2 + 1;
    const int G0 = (row0 >> 5) * 256 + jc * 32 + (row0 & 31);
    const int G1 = (row1 >> 5) * 256 + jc * 32 + (row1 & 31);

    const float* wh = dir ? whb : whf;
    const float* bh = dir ? bhb : bhf;
    const float bh0 = bh[G0], bh1 = bh[G1];

    unsigned long long wp0[16], wp1[16];
    {
        const float* w0s = wh + (long)G0 * NH2 + ks * 32;
        const float* w1s = wh + (long)G1 * NH2 + ks * 32;
#pragma unroll
        for (int i = 0; i < 16; i++) {
            wp0[i] = pack2(w0s[2 * i], w0s[2 * i + 1]);
            wp1[i] = pack2(w1s[2 * i], w1s[2 * i + 1]);
        }
    }

    const int ju = tid & 31, bu = tid >> 5;
    const int jglob = jc * 32 + ju;
    const int bglob = bg * 4 + bu;
    const float* xgp = g_xg + ((size_t)dir * NB + bglob) * NS * NG3;
    float* hxg = g_hx + grp * 2048;
    unsigned* myflag = &g_flag[(grp * 8 + jc) * 32];

    const int cb = tid >> 6, cc0 = tid & 63;
    const int csw = ((cc0 >> 3) << 3) | ((cc0 & 7) ^ (cc0 >> 3));
    float* shdst = &sh_h[cb * 256 + csw * 4];

    // group maxlen (same for all 8 blocks of the group)
    const int l0 = __ldg(lengths + bg * 4);
    const int l1 = __ldg(lengths + bg * 4 + 1);
    const int l2 = __ldg(lengths + bg * 4 + 2);
    const int l3 = __ldg(lengths + bg * 4 + 3);
    const int nsteps = max(max(l0, l1), max(l2, l3));

    for (int i = tid; i < 1024; i += 384) sh_h[i] = 0.f;
    // zero-fill outputs for skipped steps s in [nsteps, NS)
    if (tid < 128) {
        for (int s = nsteps; s < NS; s++)
            g_gru[((size_t)bglob * NS + s) * ND + dir * NH2 + jglob] = 0.f;
    }
    float hreg = 0.f;
    __syncthreads();

    for (int tt = 0; tt < nsteps; tt++) {
        const int s = dir ? (nsteps - 1 - tt) : tt;
        float xr = 0.f, xz = 0.f, xn = 0.f;
        int mk = 0;
        if (tid < 128) {
            const float* xrow = xgp + (size_t)s * NG3;
            xr = __ldg(xrow + jglob);
            xz = __ldg(xrow + NH2 + jglob);
            xn = __ldg(xrow + 2 * NH2 + jglob);
            mk = __ldg(masks + bglob * NS + s);
        }
        if (tt > 0) {
            if (tid < 8) {
                const unsigned* fp = &g_flag[(grp * 8 + tid) * 32];
                unsigned v;
                do {
                    asm volatile("ld.global.acquire.gpu.u32 %0, [%1];"
                                 : "=r"(v) : "l"(fp) : "memory");
                } while (v < (unsigned)tt);
            }
            __syncthreads();
            if (tid < 256) {
                const float4* src = (const float4*)(hxg + ((tt - 1) & 1) * 1024);
                float4 hv4;
                asm volatile("ld.global.cg.v4.f32 {%0,%1,%2,%3}, [%4];"
                             : "=f"(hv4.x), "=f"(hv4.y), "=f"(hv4.z), "=f"(hv4.w)
                             : "l"(src + tid) : "memory");
                *(float4*)shdst = hv4;
            }
            __syncthreads();
        }
        unsigned long long a0[4] = {0ull, 0ull, 0ull, 0ull};
        unsigned long long a1[4] = {0ull, 0ull, 0ull, 0ull};
#pragma unroll
        for (int i = 0; i < 8; i++) {
            const int coff = (((ks << 3) | (i ^ ks)) << 2);
#pragma unroll
            for (int b = 0; b < 4; b++) {
                ulonglong2 hv = *(const ulonglong2*)(sh_h + b * 256 + coff);
                a0[b] = fma2(wp0[2 * i],     hv.x, a0[b]);
                a0[b] = fma2(wp0[2 * i + 1], hv.y, a0[b]);
                a1[b] = fma2(wp1[2 * i],     hv.x, a1[b]);
                a1[b] = fma2(wp1[2 * i + 1], hv.y, a1[b]);
            }
        }
        float v0[4], v1[4];
#pragma unroll
        for (int b = 0; b < 4; b++) {
            float lo, hi;
            unpack2(a0[b], lo, hi); v0[b] = lo + hi;
            unpack2(a1[b], lo, hi); v1[b] = lo + hi;
        }
#pragma unroll
        for (int off = 1; off < 8; off <<= 1) {
#pragma unroll
            for (int b = 0; b < 4; b++) {
                v0[b] += __shfl_xor_sync(~0u, v0[b], off);
                v1[b] += __shfl_xor_sync(~0u, v1[b], off);
            }
        }
        if (ks == 0) {
            float4 f0 = make_float4(v0[0] + bh0, v0[1] + bh0, v0[2] + bh0, v0[3] + bh0);
            float4 f1 = make_float4(v1[0] + bh1, v1[1] + bh1, v1[2] + bh1, v1[3] + bh1);
            *(float4*)&sh_gate[rg * 8]     = f0;
            *(float4*)&sh_gate[rg * 8 + 4] = f1;
        }
        __syncthreads();
        if (tid < 128) {
            const float hgr = sh_gate[ju * 4 + bu];
            const float hgz = sh_gate[(32 + ju) * 4 + bu];
            const float hgn = sh_gate[(64 + ju) * 4 + bu];
            const float rr = 1.f / (1.f + __expf(-(xr + hgr)));
            const float zz = 1.f / (1.f + __expf(-(xz + hgz)));
            const float na = xn + rr * hgn;
            const float nn = 2.f / (1.f + __expf(-2.f * na)) - 1.f;
            const float hnew = (1.f - zz) * nn + zz * hreg;
            hreg = mk ? hnew : hreg;
            g_gru[((size_t)bglob * NS + s) * ND + dir * NH2 + jglob] = mk ? hreg : 0.f;
            if (tt == nsteps - 1) {
                hid_out[bglob * ND + dir * NH2 + jglob] = hreg;
            } else {
                __stcg(hxg + (tt & 1) * 1024 + bu * 256 + jglob, hreg);
            }
        }
        if (tt < nsteps - 1) {
            __syncthreads();
            if (tid == 0) {
                __threadfence();
                unsigned nv = (unsigned)(tt + 1);
                asm volatile("st.global.cg.u32 [%0], %1;"
                             :: "l"(myflag), "r"(nv) : "memory");
            }
        }
    }
}

// ------------------------- layernorm (optionally fused residual) ------------
__global__ void __launch_bounds__(128) ln_kernel(
    const float* __restrict__ x, const float* __restrict__ y,
    const float* __restrict__ gam, const float* __restrict__ bet,
    float* __restrict__ out)
{
    __shared__ float red[8];
    const int row = blockIdx.x;
    const int tid = threadIdx.x;
    float4 v = *(const float4*)(x + (size_t)row * ND + tid * 4);
    if (y) {
        float4 w = *(const float4*)(y + (size_t)row * ND + tid * 4);
        v.x += w.x; v.y += w.y; v.z += w.z; v.w += w.w;
    }
    float s1 = v.x + v.y + v.z + v.w;
    float s2 = v.x * v.x + v.y * v.y + v.z * v.z + v.w * v.w;
#pragma unroll
    for (int o = 16; o; o >>= 1) {
        s1 += __shfl_xor_sync(~0u, s1, o);
        s2 += __shfl_xor_sync(~0u, s2, o);
    }
    const int wid = tid >> 5;
    if ((tid & 31) == 0) { red[wid] = s1; red[wid + 4] = s2; }
    __syncthreads();
    s1 = red[0] + red[1] + red[2] + red[3];
    s2 = red[4] + red[5] + red[6] + red[7];
    const float mu = s1 * (1.f / ND);
    const float var = s2 * (1.f / ND) - mu * mu;
    const float rs = rsqrtf(var + 1e-5f);
    const float4 gv = *(const float4*)(gam + tid * 4);
    const float4 bv = *(const float4*)(bet + tid * 4);
    float4 o4;
    o4.x = (v.x - mu) * rs * gv.x + bv.x;
    o4.y = (v.y - mu) * rs * gv.y + bv.y;
    o4.z = (v.z - mu) * rs * gv.z + bv.z;
    o4.w = (v.w - mu) * rs * gv.w + bv.w;
    *(float4*)(out + (size_t)row * ND + tid * 4) = o4;
}

// ------------------------- launch -------------------------
extern "C" void kernel_launch(void* const* d_in, const int* in_sizes, int n_in,
                              void* d_out, int out_size)
{
    const float* splits = (const float*)d_in[0];
    const float* w_ih_f = (const float*)d_in[1];
    const float* w_hh_f = (const float*)d_in[2];
    const float* b_ih_f = (const float*)d_in[3];
    const float* b_hh_f = (const float*)d_in[4];
    const float* w_ih_b = (const float*)d_in[5];
    const float* w_hh_b = (const float*)d_in[6];
    const float* b_ih_b = (const float*)d_in[7];
    const float* b_hh_b = (const float*)d_in[8];
    const float* ln1_g  = (const float*)d_in[9];
    const float* ln1_b  = (const float*)d_in[10];
    const float* wq = (const float*)d_in[11];
    const float* bq = (const float*)d_in[12];
    const float* wk = (const float*)d_in[13];
    const float* bk = (const float*)d_in[14];
    const float* wv = (const float*)d_in[15];
    const float* bv = (const float*)d_in[16];
    const float* wo = (const float*)d_in[17];
    const float* bo = (const float*)d_in[18];
    const float* ln2_g = (const float*)d_in[19];
    const float* ln2_b = (const float*)d_in[20];
    const int* lengths = (const int*)d_in[21];
    const int* masks   = (const int*)d_in[22];
    float* out = (float*)d_out;

    float *xg, *gru, *ln1, *q, *k, *vt, *cc, *oo;
    cudaGetSymbolAddress((void**)&xg,  g_xg);
    cudaGetSymbolAddress((void**)&gru, g_gru);
    cudaGetSymbolAddress((void**)&ln1, g_ln1);
    cudaGetSymbolAddress((void**)&q,   g_q);
    cudaGetSymbolAddress((void**)&k,   g_k);
    cudaGetSymbolAddress((void**)&vt,  g_vt);
    cudaGetSymbolAddress((void**)&cc,  g_cc);
    cudaGetSymbolAddress((void**)&oo,  g_o);

    const int M = NB * NS;  // 16384
    const int ATTN_SMEM = ATTN_SMEM_FLOATS * 4;
    cudaFuncSetAttribute(attn_kernel, cudaFuncAttributeMaxDynamicSharedMemorySize, ATTN_SMEM);
    cudaFuncSetAttribute(gemm3, cudaFuncAttributeMaxDynamicSharedMemorySize, G3_SMEM);

    // GRU input projections — one launch, z = dir; prefix-mask tile skip
    gemm3<<<dim3(6, 128, 2), 256, G3_SMEM>>>(
        splits, w_ih_f, w_ih_b, nullptr, b_ih_f, b_ih_b, nullptr,
        xg, xg + (size_t)M * NG3, nullptr, 0, 0, 0,
        M, NG3, ND, masks);
    // GRU recurrence (persistent, per-rank flag sync; length-aware step skip)
    reset_kernel<<<16, 256>>>();
    gru_kernel<<<128, 384>>>(w_hh_f, w_hh_b, b_hh_f, b_hh_b, masks, lengths,
                             out + (size_t)NB * NS * ND);
    // LN1
    ln_kernel<<<M, 128>>>(gru, nullptr, ln1_g, ln1_b, ln1);
    // Q/K/V projections — one launch, z = {q, k, v}; prefix-mask tile skip
    gemm3<<<dim3(4, 128, 3), 256, G3_SMEM>>>(
        ln1, wq, wk, wv, bq, bk, bv,
        q, k, vt, 1, 1, 2,
        M, ND, ND, masks);
    // fused attention: scores + masked online softmax + PV -> concat
    attn_kernel<<<dim3(4, 256), 256, ATTN_SMEM>>>(q, k, vt, cc, lengths);
    // out projection + row mask (skip writes zero tiles)
    gemm3<<<dim3(4, 128, 1), 256, G3_SMEM>>>(
        cc, wo, nullptr, nullptr, bo, nullptr, nullptr,
        oo, nullptr, nullptr, 5, 5, 5,
        M, ND, ND, masks);
    // residual + LN2 -> final outputs
    ln_kernel<<<M, 128>>>(ln1, oo, ln2_g, ln2_b, out);
}